// round 6
// baseline (speedup 1.0000x reference)
#include <cuda_runtime.h>
#include <cuda_bf16.h>
#include <cuda_fp16.h>
#include <cstdint>
#include <cfloat>

#define BB   16
#define NN   1024
#define DD   1024
#define PP   256
#define KNB  16
#define MM   (BB * NN)     // 16384

// ===================== helpers ==============================================
__device__ __forceinline__ uint32_t smem_u32(const void* p) {
    uint32_t a;
    asm("{ .reg .u64 t; cvta.to.shared.u64 t, %1; cvt.u32.u64 %0, t; }" : "=r"(a) : "l"(p));
    return a;
}
__device__ __forceinline__ uint64_t cvta_g(const void* p) {
    uint64_t r; asm("cvta.to.global.u64 %0, %1;" : "=l"(r) : "l"(p)); return r;
}
#define SMEM_SWIZZLE_128B(off) ((off) ^ (((off) >> 3) & 0x70))

#define CP_ASYNC16(dst, src) \
    asm volatile("cp.async.cg.shared.global [%0], [%1], 16;" :: "r"(dst), "l"(src) : "memory")
#define CP_COMMIT() asm volatile("cp.async.commit_group;" ::: "memory")
#define CP_WAIT(n)  asm volatile("cp.async.wait_group %0;" :: "n"(n) : "memory")

#define LDSM_X4(r0, r1, r2, r3, addr) \
    asm volatile("ldmatrix.sync.aligned.m8n8.x4.shared.b16 {%0,%1,%2,%3}, [%4];" \
                 : "=r"(r0), "=r"(r1), "=r"(r2), "=r"(r3) : "r"(addr))

#define MMA_F16(d, a, b) \
    asm volatile("mma.sync.aligned.m16n8k16.row.col.f32.f16.f16.f32 " \
                 "{%0,%1,%2,%3}, {%4,%5,%6,%7}, {%8,%9}, {%0,%1,%2,%3};" \
                 : "+f"((d)[0]), "+f"((d)[1]), "+f"((d)[2]), "+f"((d)[3]) \
                 : "r"((a)[0]), "r"((a)[1]), "r"((a)[2]), "r"((a)[3]), \
                   "r"((b)[0]), "r"((b)[1]))

// ===================== scratch ==============================================
__device__ __half g_fa[(size_t)MM * DD];      // features fp16 [M][1024]
__device__ __half g_wdT_h[PP * DD];           // W_down^T hi/lo fp16 [256][1024]
__device__ __half g_wdT_l[PP * DD];
__device__ __half g_wcT_h[2 * PP * PP];       // Wcomb^T hi/lo fp16 [512][256]
__device__ __half g_wcT_l[2 * PP * PP];
__device__ __half g_wuT_h[DD * PP];           // W_up^T hi/lo fp16 [1024][256]
__device__ __half g_wuT_l[DD * PP];
__device__ __half g_fl[(size_t)MM * PP];      // feats_low fp16 [M][256]
__device__ __half g_AB[(size_t)MM * 2 * PP];  // fp16 [M][0:256]=A',[256:512]=Bv
__device__ __half g_loc[(size_t)MM * PP];     // local fp16 [M][256]
__device__ int    g_idx[MM * KNB];
__device__ float  g_s[PP];
__device__ float  g_t[PP];

__device__ __forceinline__ void split_hf(float v, __half& h, __half& l) {
    h = __float2half_rn(v);
    l = __float2half_rn(v - __half2float(h));
}

// ===================== prep kernels =========================================
__global__ void split_features_kernel(const float4* __restrict__ f) {
    int i = blockIdx.x * blockDim.x + threadIdx.x;
    if (i >= MM * DD / 4) return;
    float4 v = f[i];
    __half hh[4];
    hh[0] = __float2half_rn(v.x);
    hh[1] = __float2half_rn(v.y);
    hh[2] = __float2half_rn(v.z);
    hh[3] = __float2half_rn(v.w);
    *(uint2*)(g_fa + 4 * (size_t)i) = *(uint2*)hh;
}

__global__ void prep_weights_kernel(const float* __restrict__ W_down,
                                    const float* __restrict__ W_edge,
                                    const float* __restrict__ W_up,
                                    const float* __restrict__ b_edge,
                                    const float* __restrict__ gamma,
                                    const float* __restrict__ beta,
                                    const float* __restrict__ mean,
                                    const float* __restrict__ var) {
    int t = blockIdx.x * blockDim.x + threadIdx.x;
    if (t < PP * DD) {
        float v = W_down[(size_t)(t & 1023) * PP + (t >> 10)];
        split_hf(v, g_wdT_h[t], g_wdT_l[t]);
    }
    if (t < DD * PP) {
        float v = W_up[(size_t)(t & 255) * DD + (t >> 8)];
        split_hf(v, g_wuT_h[t], g_wuT_l[t]);
    }
    if (t < 2 * PP * PP) {
        int p = t >> 8, f = t & 255;
        float v = (p < PP) ? (W_edge[f * PP + p] - W_edge[(f + PP) * PP + p])
                           : W_edge[(f + PP) * PP + (p - PP)];
        split_hf(v, g_wcT_h[t], g_wcT_l[t]);
    }
    if (t < PP) {
        float rs = rsqrtf(var[t] + 1e-5f);
        float sv = gamma[t] * rs;
        g_s[t] = sv;
        g_t[t] = beta[t] - mean[t] * sv + sv * b_edge[t];
    }
}

// ===================== KNN: warp-per-point min-extraction ===================
// Each warp owns one point. Lane holds 32 candidates (m = j*32+lane), packed
// as signed 64-bit keys (float bits << 32 | m) -> exact distance order with
// stable smallest-index tie-break. 16 rounds of warp-argmin extraction.
__global__ __launch_bounds__(256) void knn_kernel(const float* __restrict__ pts) {
    const int b    = blockIdx.y;
    const int warp = threadIdx.x >> 5;
    const int lane = threadIdx.x & 31;
    const int n    = blockIdx.x * 8 + warp;

    __shared__ float4 sp[NN];     // 16 KB: (x, y, z, |p|^2)
    for (int m = threadIdx.x; m < NN; m += 256) {
        float x = pts[((size_t)b * NN + m) * 3 + 0];
        float y = pts[((size_t)b * NN + m) * 3 + 1];
        float z = pts[((size_t)b * NN + m) * 3 + 2];
        sp[m] = make_float4(x, y, z, fmaf(x, x, fmaf(y, y, z * z)));
    }
    __syncthreads();

    const float4 P = sp[n];

    long long key[32];
#pragma unroll
    for (int j = 0; j < 32; ++j) {
        const int m = j * 32 + lane;
        float4 q = sp[m];
        float dot = fmaf(P.x, q.x, fmaf(P.y, q.y, P.z * q.z));
        float d = fmaf(-2.0f, dot, P.w + q.w);
        key[j] = ((long long)(int)__float_as_uint(d) << 32) | (unsigned)m;
    }

    long long pmin = key[0];
#pragma unroll
    for (int j = 1; j < 32; ++j) pmin = key[j] < pmin ? key[j] : pmin;

    const int base = ((b << 10) + n) * KNB;
    const long long DEAD = 0x7FFFFFFFFFFFFFFFLL;

#pragma unroll
    for (int r = 0; r < KNB; ++r) {
        long long g = pmin;
#pragma unroll
        for (int s = 16; s; s >>= 1) {
            long long o = __shfl_xor_sync(0xffffffffu, g, s);
            g = o < g ? o : g;
        }
        if (lane == 0) g_idx[base + r] = (int)(g & 1023);
        if (r == KNB - 1) break;

        const int mwin = (int)(g & 1023);
        const int jown = ((mwin & 31) == lane) ? (mwin >> 5) : 64;
        pmin = DEAD;
#pragma unroll
        for (int j = 0; j < 32; ++j) {
            key[j] = (j == jown) ? DEAD : key[j];
            pmin = key[j] < pmin ? key[j] : pmin;
        }
    }
}

// ===================== edge gather + BN + relu + max ========================
__global__ __launch_bounds__(256) void edge_max_kernel() {
    const int bn = blockIdx.x;
    const int p  = threadIdx.x;
    const int b  = bn >> 10;

    __shared__ int sidx[KNB];
    if (p < KNB) sidx[p] = g_idx[bn * KNB + p];
    __syncthreads();

    const float a  = __half2float(g_AB[(size_t)bn * 512 + p]);
    const float sp = g_s[p];
    const float tp = g_t[p];

    float acc = 0.0f;
#pragma unroll
    for (int k = 0; k < KNB; ++k) {
        float v = __half2float(g_AB[(size_t)((b << 10) + sidx[k]) * 512 + PP + p]);
        float h = fmaf(sp, a + v, tp);
        acc = fmaxf(acc, h);
    }
    g_loc[(size_t)bn * PP + p] = __float2half_rn(acc);
}

// ===================== GEMM fp16 2-term, 2-stage, k-chunk 64 ================
// C = A(fp16) @ (Bh+Bl)^T ; B stored [N][K].
// EPI 0: store fp16 ; EPI 1: relu(acc+bias) -> fp16 ; EPI 2: acc+bias+res -> f32.
template <int EPI>
__global__ void __launch_bounds__(256, 2) gemm_f16_2t(
    const __half* __restrict__ A,
    const __half* __restrict__ Bh, const __half* __restrict__ Bl,
    int K, int Nc,
    __half* __restrict__ Ch, float* __restrict__ Cf,
    const float* __restrict__ bias, const float* __restrict__ res)
{
    extern __shared__ char smraw[];
    const uint32_t smb = smem_u32(smraw);   // 2 buffers x 48KB: [A | Bh | Bl]
    const int tid = threadIdx.x, lane = tid & 31, wid = tid >> 5;
    const int warp_m = wid & 3, warp_n = wid >> 2;
    const int bm = blockIdx.y, bn = blockIdx.x;

    const uint64_t gA  = cvta_g(A  + (size_t)(bm * 128) * K);
    const uint64_t gBh = cvta_g(Bh + (size_t)(bn * 128) * K);
    const uint64_t gBl = cvta_g(Bl + (size_t)(bn * 128) * K);
    const int nk = K >> 6;

    const int grp = lane >> 3, rr = lane & 7;
    const int a_row0 = warp_m * 32 + ((grp & 1) << 3) + rr;
    const int kadd_a = (grp >> 1) << 4;
    const int b_row0 = warp_n * 64 + ((grp >> 1) << 3) + rr;
    const int kadd_b = (grp & 1) << 4;

    float acc[2][8][4];
#pragma unroll
    for (int i = 0; i < 2; ++i)
#pragma unroll
        for (int j = 0; j < 8; ++j)
#pragma unroll
            for (int c = 0; c < 4; ++c) acc[i][j][c] = 0.0f;

    auto issue = [&](int kc) {
        const uint32_t bb = (uint32_t)(kc & 1) * 49152u;
        const int kof = kc * 64;
#pragma unroll
        for (int i = 0; i < 4; ++i) {
            int idx = i * 256 + tid;
            int row = idx >> 3, g = idx & 7;
            int kel = kof + g * 8;
            uint32_t dst = SMEM_SWIZZLE_128B((uint32_t)(row * 128 + g * 16));
            size_t src = (size_t)row * K + kel;
            CP_ASYNC16(smb + bb + dst,         gA  + src * 2);
            CP_ASYNC16(smb + bb + 16384 + dst, gBh + src * 2);
            CP_ASYNC16(smb + bb + 32768 + dst, gBl + src * 2);
        }
    };

    issue(0); CP_COMMIT();

    for (int kc = 0; kc < nk; ++kc) {
        if (kc + 1 < nk) issue(kc + 1);
        CP_COMMIT();
        CP_WAIT(1);
        __syncthreads();

        const uint32_t bufA  = smb + (uint32_t)(kc & 1) * 49152u;
        const uint32_t bufBh = bufA + 16384;
        const uint32_t bufBl = bufA + 32768;

#pragma unroll
        for (int s = 0; s < 4; ++s) {
            uint32_t af[2][4];
#pragma unroll
            for (int mt = 0; mt < 2; ++mt) {
                int row = a_row0 + mt * 16;
                uint32_t rb = bufA + row * 128;
                uint32_t xr = (row & 7) << 4;
                LDSM_X4(af[mt][0], af[mt][1], af[mt][2], af[mt][3],
                        rb + (((uint32_t)(s * 32 + kadd_a)) ^ xr));
            }
#pragma unroll
            for (int jg = 0; jg < 2; ++jg) {
                uint32_t bh[4][2], bl[4][2];
#pragma unroll
                for (int p = 0; p < 2; ++p) {
                    int row = b_row0 + jg * 32 + p * 16;
                    uint32_t xr = (row & 7) << 4;
                    uint32_t by = (uint32_t)(s * 32 + kadd_b);
                    LDSM_X4(bh[2 * p][0], bh[2 * p][1], bh[2 * p + 1][0], bh[2 * p + 1][1],
                            bufBh + row * 128 + (by ^ xr));
                    LDSM_X4(bl[2 * p][0], bl[2 * p][1], bl[2 * p + 1][0], bl[2 * p + 1][1],
                            bufBl + row * 128 + (by ^ xr));
                }
#pragma unroll
                for (int mt = 0; mt < 2; ++mt)
#pragma unroll
                    for (int j = 0; j < 4; ++j) {
                        float* d = acc[mt][jg * 4 + j];
                        MMA_F16(d, af[mt], bh[j]);
                        MMA_F16(d, af[mt], bl[j]);
                    }
            }
        }
        __syncthreads();
    }

#pragma unroll
    for (int mt = 0; mt < 2; ++mt)
#pragma unroll
        for (int half = 0; half < 2; ++half) {
            size_t row = (size_t)bm * 128 + warp_m * 32 + mt * 16 + half * 8 + (lane >> 2);
#pragma unroll
            for (int j = 0; j < 8; ++j) {
                int col = bn * 128 + warp_n * 64 + j * 8 + 2 * (lane & 3);
                float v0 = acc[mt][j][half * 2 + 0];
                float v1 = acc[mt][j][half * 2 + 1];
                if (EPI == 0) {
                    __half2 hv; hv.x = __float2half_rn(v0); hv.y = __float2half_rn(v1);
                    *(__half2*)(Ch + row * Nc + col) = hv;
                } else if (EPI == 1) {
                    v0 = fmaxf(v0 + bias[col], 0.0f);
                    v1 = fmaxf(v1 + bias[col + 1], 0.0f);
                    __half2 hv; hv.x = __float2half_rn(v0); hv.y = __float2half_rn(v1);
                    *(__half2*)(Ch + row * Nc + col) = hv;
                } else {
                    float2 r = *(const float2*)(res + row * Nc + col);
                    *(float2*)(Cf + row * Nc + col) =
                        make_float2(v0 + bias[col] + r.x, v1 + bias[col + 1] + r.y);
                }
            }
        }
}

// ===================== launch ===============================================
extern "C" void kernel_launch(void* const* d_in, const int* in_sizes, int n_in,
                              void* d_out, int out_size)
{
    const float* points   = (const float*)d_in[0];
    const float* features = (const float*)d_in[1];
    const float* W_down   = (const float*)d_in[2];
    const float* b_down   = (const float*)d_in[3];
    const float* W_edge   = (const float*)d_in[4];
    const float* b_edge   = (const float*)d_in[5];
    const float* gamma    = (const float*)d_in[6];
    const float* beta     = (const float*)d_in[7];
    const float* mean     = (const float*)d_in[8];
    const float* var      = (const float*)d_in[9];
    const float* W_up     = (const float*)d_in[10];
    const float* b_up     = (const float*)d_in[11];
    float* out = (float*)d_out;

    const int SMEM_DYN = 98304;
    static bool attr_done = false;
    if (!attr_done) {
        cudaFuncSetAttribute(gemm_f16_2t<0>, cudaFuncAttributeMaxDynamicSharedMemorySize, SMEM_DYN);
        cudaFuncSetAttribute(gemm_f16_2t<1>, cudaFuncAttributeMaxDynamicSharedMemorySize, SMEM_DYN);
        cudaFuncSetAttribute(gemm_f16_2t<2>, cudaFuncAttributeMaxDynamicSharedMemorySize, SMEM_DYN);
        attr_done = true;
    }

    void *p_fa, *p_wdh, *p_wdl, *p_wch, *p_wcl, *p_wuh, *p_wul;
    void *p_fl, *p_ab, *p_loc;
    cudaGetSymbolAddress(&p_fa,  g_fa);
    cudaGetSymbolAddress(&p_wdh, g_wdT_h); cudaGetSymbolAddress(&p_wdl, g_wdT_l);
    cudaGetSymbolAddress(&p_wch, g_wcT_h); cudaGetSymbolAddress(&p_wcl, g_wcT_l);
    cudaGetSymbolAddress(&p_wuh, g_wuT_h); cudaGetSymbolAddress(&p_wul, g_wuT_l);
    cudaGetSymbolAddress(&p_fl,  g_fl);
    cudaGetSymbolAddress(&p_ab,  g_AB);
    cudaGetSymbolAddress(&p_loc, g_loc);

    // 1) prep + split + KNN
    prep_weights_kernel<<<(PP * DD + 255) / 256, 256>>>(
        W_down, W_edge, W_up, b_edge, gamma, beta, mean, var);
    split_features_kernel<<<(MM * DD / 4 + 255) / 256, 256>>>((const float4*)features);
    knn_kernel<<<dim3(NN / 8, BB), 256>>>(points);

    // 2) feats_low = relu(features @ W_down + b_down)  [M=16384, N=256, K=1024]
    gemm_f16_2t<1><<<dim3(PP / 128, MM / 128), 256, SMEM_DYN>>>(
        (const __half*)p_fa, (const __half*)p_wdh, (const __half*)p_wdl,
        DD, PP, (__half*)p_fl, nullptr, b_down, nullptr);

    // 3) AB = feats_low @ Wcomb                        [M, N=512, K=256]
    gemm_f16_2t<0><<<dim3(2 * PP / 128, MM / 128), 256, SMEM_DYN>>>(
        (const __half*)p_fl, (const __half*)p_wch, (const __half*)p_wcl,
        PP, 2 * PP, (__half*)p_ab, nullptr, nullptr, nullptr);

    // 4) gather + BN + relu + max over K -> local (fp16)
    edge_max_kernel<<<MM, 256>>>();

    // 5) out = features + local @ W_up + b_up          [M, N=1024, K=256]
    gemm_f16_2t<2><<<dim3(DD / 128, MM / 128), 256, SMEM_DYN>>>(
        (const __half*)p_loc, (const __half*)p_wuh, (const __half*)p_wul,
        PP, DD, nullptr, out, b_up, features);
}

// round 7
// speedup vs baseline: 1.2678x; 1.2678x over previous
#include <cuda_runtime.h>
#include <cuda_bf16.h>
#include <cuda_fp16.h>
#include <cstdint>
#include <cfloat>

#define BB   16
#define NN   1024
#define DD   1024
#define PP   256
#define KNB  16
#define MM   (BB * NN)     // 16384

// ===================== helpers ==============================================
__device__ __forceinline__ uint32_t smem_u32(const void* p) {
    uint32_t a;
    asm("{ .reg .u64 t; cvta.to.shared.u64 t, %1; cvt.u32.u64 %0, t; }" : "=r"(a) : "l"(p));
    return a;
}
__device__ __forceinline__ uint64_t cvta_g(const void* p) {
    uint64_t r; asm("cvta.to.global.u64 %0, %1;" : "=l"(r) : "l"(p)); return r;
}
#define SMEM_SWIZZLE_128B(off) ((off) ^ (((off) >> 3) & 0x70))

#define CP_ASYNC16(dst, src) \
    asm volatile("cp.async.cg.shared.global [%0], [%1], 16;" :: "r"(dst), "l"(src) : "memory")
#define CP_COMMIT() asm volatile("cp.async.commit_group;" ::: "memory")
#define CP_WAIT(n)  asm volatile("cp.async.wait_group %0;" :: "n"(n) : "memory")

#define LDSM_X4(r0, r1, r2, r3, addr) \
    asm volatile("ldmatrix.sync.aligned.m8n8.x4.shared.b16 {%0,%1,%2,%3}, [%4];" \
                 : "=r"(r0), "=r"(r1), "=r"(r2), "=r"(r3) : "r"(addr))

#define MMA_F16(d, a, b) \
    asm volatile("mma.sync.aligned.m16n8k16.row.col.f32.f16.f16.f32 " \
                 "{%0,%1,%2,%3}, {%4,%5,%6,%7}, {%8,%9}, {%0,%1,%2,%3};" \
                 : "+f"((d)[0]), "+f"((d)[1]), "+f"((d)[2]), "+f"((d)[3]) \
                 : "r"((a)[0]), "r"((a)[1]), "r"((a)[2]), "r"((a)[3]), \
                   "r"((b)[0]), "r"((b)[1]))

// ===================== scratch ==============================================
__device__ __half g_fa[(size_t)MM * DD];      // features fp16 [M][1024]
__device__ __half g_wdT_h[PP * DD];           // W_down^T hi/lo fp16 [256][1024]
__device__ __half g_wdT_l[PP * DD];
__device__ __half g_wcT_h[2 * PP * PP];       // Wcomb^T hi/lo fp16 [512][256]
__device__ __half g_wcT_l[2 * PP * PP];
__device__ __half g_wuT_h[DD * PP];           // W_up^T hi/lo fp16 [1024][256]
__device__ __half g_wuT_l[DD * PP];
__device__ __half g_fl[(size_t)MM * PP];      // feats_low fp16 [M][256]
__device__ __half g_AB[(size_t)MM * 2 * PP];  // fp16 [M][0:256]=A',[256:512]=Bv
__device__ __half g_loc[(size_t)MM * PP];     // local fp16 [M][256]
__device__ int    g_idx[MM * KNB];
__device__ float  g_s[PP];
__device__ float  g_t[PP];

__device__ __forceinline__ void split_hf(float v, __half& h, __half& l) {
    h = __float2half_rn(v);
    l = __float2half_rn(v - __half2float(h));
}

// ===================== prep kernels =========================================
__global__ void split_features_kernel(const float4* __restrict__ f) {
    int i = blockIdx.x * blockDim.x + threadIdx.x;
    if (i >= MM * DD / 4) return;
    float4 v = f[i];
    __half hh[4];
    hh[0] = __float2half_rn(v.x);
    hh[1] = __float2half_rn(v.y);
    hh[2] = __float2half_rn(v.z);
    hh[3] = __float2half_rn(v.w);
    *(uint2*)(g_fa + 4 * (size_t)i) = *(uint2*)hh;
}

__global__ void prep_weights_kernel(const float* __restrict__ W_down,
                                    const float* __restrict__ W_edge,
                                    const float* __restrict__ W_up,
                                    const float* __restrict__ b_edge,
                                    const float* __restrict__ gamma,
                                    const float* __restrict__ beta,
                                    const float* __restrict__ mean,
                                    const float* __restrict__ var) {
    int t = blockIdx.x * blockDim.x + threadIdx.x;
    if (t < PP * DD) {
        float v = W_down[(size_t)(t & 1023) * PP + (t >> 10)];
        split_hf(v, g_wdT_h[t], g_wdT_l[t]);
    }
    if (t < DD * PP) {
        float v = W_up[(size_t)(t & 255) * DD + (t >> 8)];
        split_hf(v, g_wuT_h[t], g_wuT_l[t]);
    }
    if (t < 2 * PP * PP) {
        int p = t >> 8, f = t & 255;
        float v = (p < PP) ? (W_edge[f * PP + p] - W_edge[(f + PP) * PP + p])
                           : W_edge[(f + PP) * PP + (p - PP)];
        split_hf(v, g_wcT_h[t], g_wcT_l[t]);
    }
    if (t < PP) {
        float rs = rsqrtf(var[t] + 1e-5f);
        float sv = gamma[t] * rs;
        g_s[t] = sv;
        g_t[t] = beta[t] - mean[t] * sv + sv * b_edge[t];
    }
}

// ===================== KNN: warp-per-point, 32-bit exact extraction =========
// Lane holds 32 candidate distances (m = j*32 + lane) as plain floats (exact).
// 16 rounds: fminf warp-reduce finds exact min value; owner identified by
// exact compare; ties broken by integer min over m (= top_k's smallest-index
// rule); single winner invalidates its copy.
__global__ __launch_bounds__(256) void knn_kernel(const float* __restrict__ pts) {
    const int b    = blockIdx.y;
    const int warp = threadIdx.x >> 5;
    const int lane = threadIdx.x & 31;
    const int n    = blockIdx.x * 8 + warp;

    __shared__ float4 sp[NN];     // 16 KB: (x, y, z, |p|^2)
    for (int m = threadIdx.x; m < NN; m += 256) {
        float x = pts[((size_t)b * NN + m) * 3 + 0];
        float y = pts[((size_t)b * NN + m) * 3 + 1];
        float z = pts[((size_t)b * NN + m) * 3 + 2];
        sp[m] = make_float4(x, y, z, fmaf(x, x, fmaf(y, y, z * z)));
    }
    __syncthreads();

    const float4 P = sp[n];
    const float BIGF = 3.0e38f;

    float d[32];
    float pmin = BIGF;
#pragma unroll
    for (int j = 0; j < 32; ++j) {
        float4 q = sp[j * 32 + lane];
        float dot = fmaf(P.x, q.x, fmaf(P.y, q.y, P.z * q.z));
        d[j] = fmaf(-2.0f, dot, P.w + q.w);
        pmin = fminf(pmin, d[j]);
    }

    const int base = ((b << 10) + n) * KNB;

#pragma unroll
    for (int r = 0; r < KNB; ++r) {
        // exact global min value
        float g = pmin;
#pragma unroll
        for (int s = 16; s; s >>= 1)
            g = fminf(g, __shfl_xor_sync(0xffffffffu, g, s));

        // smallest local j holding g (only meaningful when pmin == g)
        int jm = 99;
#pragma unroll
        for (int j = 31; j >= 0; --j)
            jm = (d[j] == g) ? j : jm;

        int mc = (pmin == g) ? (jm * 32 + lane) : 0x7FFFFFFF;
#pragma unroll
        for (int s = 16; s; s >>= 1) {
            int o = __shfl_xor_sync(0xffffffffu, mc, s);
            mc = o < mc ? o : mc;
        }
        if (lane == 0) g_idx[base + r] = mc;
        if (r == KNB - 1) break;

        // single winner invalidates, then rescan
        const int jkill = (lane == (mc & 31)) ? (mc >> 5) : 64;
        pmin = BIGF;
#pragma unroll
        for (int j = 0; j < 32; ++j) {
            d[j] = (j == jkill) ? BIGF : d[j];
            pmin = fminf(pmin, d[j]);
        }
    }
}

// ===================== edge gather + BN + relu + max ========================
__global__ __launch_bounds__(256) void edge_max_kernel() {
    const int bn = blockIdx.x;
    const int p  = threadIdx.x;
    const int b  = bn >> 10;

    __shared__ int sidx[KNB];
    if (p < KNB) sidx[p] = g_idx[bn * KNB + p];
    __syncthreads();

    const float a  = __half2float(g_AB[(size_t)bn * 512 + p]);
    const float sp = g_s[p];
    const float tp = g_t[p];

    float acc = 0.0f;
#pragma unroll
    for (int k = 0; k < KNB; ++k) {
        float v = __half2float(g_AB[(size_t)((b << 10) + sidx[k]) * 512 + PP + p]);
        float h = fmaf(sp, a + v, tp);
        acc = fmaxf(acc, h);
    }
    g_loc[(size_t)bn * PP + p] = __float2half_rn(acc);
}

// ===================== GEMM fp16 2-term, 2-stage, k-chunk 64 ================
// C = A(fp16) @ (Bh+Bl)^T ; B stored [N][K].
// EPI 0: store fp16 ; EPI 1: relu(acc+bias) -> fp16 ; EPI 2: acc+bias+res -> f32.
template <int EPI>
__global__ void __launch_bounds__(256, 2) gemm_f16_2t(
    const __half* __restrict__ A,
    const __half* __restrict__ Bh, const __half* __restrict__ Bl,
    int K, int Nc,
    __half* __restrict__ Ch, float* __restrict__ Cf,
    const float* __restrict__ bias, const float* __restrict__ res)
{
    extern __shared__ char smraw[];
    const uint32_t smb = smem_u32(smraw);   // 2 buffers x 48KB: [A | Bh | Bl]
    const int tid = threadIdx.x, lane = tid & 31, wid = tid >> 5;
    const int warp_m = wid & 3, warp_n = wid >> 2;
    const int bm = blockIdx.y, bn = blockIdx.x;

    const uint64_t gA  = cvta_g(A  + (size_t)(bm * 128) * K);
    const uint64_t gBh = cvta_g(Bh + (size_t)(bn * 128) * K);
    const uint64_t gBl = cvta_g(Bl + (size_t)(bn * 128) * K);
    const int nk = K >> 6;

    const int grp = lane >> 3, rr = lane & 7;
    const int a_row0 = warp_m * 32 + ((grp & 1) << 3) + rr;
    const int kadd_a = (grp >> 1) << 4;
    const int b_row0 = warp_n * 64 + ((grp >> 1) << 3) + rr;
    const int kadd_b = (grp & 1) << 4;

    float acc[2][8][4];
#pragma unroll
    for (int i = 0; i < 2; ++i)
#pragma unroll
        for (int j = 0; j < 8; ++j)
#pragma unroll
            for (int c = 0; c < 4; ++c) acc[i][j][c] = 0.0f;

    auto issue = [&](int kc) {
        const uint32_t bb = (uint32_t)(kc & 1) * 49152u;
        const int kof = kc * 64;
#pragma unroll
        for (int i = 0; i < 4; ++i) {
            int idx = i * 256 + tid;
            int row = idx >> 3, g = idx & 7;
            int kel = kof + g * 8;
            uint32_t dst = SMEM_SWIZZLE_128B((uint32_t)(row * 128 + g * 16));
            size_t src = (size_t)row * K + kel;
            CP_ASYNC16(smb + bb + dst,         gA  + src * 2);
            CP_ASYNC16(smb + bb + 16384 + dst, gBh + src * 2);
            CP_ASYNC16(smb + bb + 32768 + dst, gBl + src * 2);
        }
    };

    issue(0); CP_COMMIT();

    for (int kc = 0; kc < nk; ++kc) {
        if (kc + 1 < nk) issue(kc + 1);
        CP_COMMIT();
        CP_WAIT(1);
        __syncthreads();

        const uint32_t bufA  = smb + (uint32_t)(kc & 1) * 49152u;
        const uint32_t bufBh = bufA + 16384;
        const uint32_t bufBl = bufA + 32768;

#pragma unroll
        for (int s = 0; s < 4; ++s) {
            uint32_t af[2][4];
#pragma unroll
            for (int mt = 0; mt < 2; ++mt) {
                int row = a_row0 + mt * 16;
                uint32_t rb = bufA + row * 128;
                uint32_t xr = (row & 7) << 4;
                LDSM_X4(af[mt][0], af[mt][1], af[mt][2], af[mt][3],
                        rb + (((uint32_t)(s * 32 + kadd_a)) ^ xr));
            }
#pragma unroll
            for (int jg = 0; jg < 2; ++jg) {
                uint32_t bh[4][2], bl[4][2];
#pragma unroll
                for (int p = 0; p < 2; ++p) {
                    int row = b_row0 + jg * 32 + p * 16;
                    uint32_t xr = (row & 7) << 4;
                    uint32_t by = (uint32_t)(s * 32 + kadd_b);
                    LDSM_X4(bh[2 * p][0], bh[2 * p][1], bh[2 * p + 1][0], bh[2 * p + 1][1],
                            bufBh + row * 128 + (by ^ xr));
                    LDSM_X4(bl[2 * p][0], bl[2 * p][1], bl[2 * p + 1][0], bl[2 * p + 1][1],
                            bufBl + row * 128 + (by ^ xr));
                }
#pragma unroll
                for (int mt = 0; mt < 2; ++mt)
#pragma unroll
                    for (int j = 0; j < 4; ++j) {
                        float* d = acc[mt][jg * 4 + j];
                        MMA_F16(d, af[mt], bh[j]);
                        MMA_F16(d, af[mt], bl[j]);
                    }
            }
        }
        __syncthreads();
    }

#pragma unroll
    for (int mt = 0; mt < 2; ++mt)
#pragma unroll
        for (int half = 0; half < 2; ++half) {
            size_t row = (size_t)bm * 128 + warp_m * 32 + mt * 16 + half * 8 + (lane >> 2);
#pragma unroll
            for (int j = 0; j < 8; ++j) {
                int col = bn * 128 + warp_n * 64 + j * 8 + 2 * (lane & 3);
                float v0 = acc[mt][j][half * 2 + 0];
                float v1 = acc[mt][j][half * 2 + 1];
                if (EPI == 0) {
                    __half2 hv; hv.x = __float2half_rn(v0); hv.y = __float2half_rn(v1);
                    *(__half2*)(Ch + row * Nc + col) = hv;
                } else if (EPI == 1) {
                    v0 = fmaxf(v0 + bias[col], 0.0f);
                    v1 = fmaxf(v1 + bias[col + 1], 0.0f);
                    __half2 hv; hv.x = __float2half_rn(v0); hv.y = __float2half_rn(v1);
                    *(__half2*)(Ch + row * Nc + col) = hv;
                } else {
                    float2 r = *(const float2*)(res + row * Nc + col);
                    *(float2*)(Cf + row * Nc + col) =
                        make_float2(v0 + bias[col] + r.x, v1 + bias[col + 1] + r.y);
                }
            }
        }
}

// ===================== launch ===============================================
extern "C" void kernel_launch(void* const* d_in, const int* in_sizes, int n_in,
                              void* d_out, int out_size)
{
    const float* points   = (const float*)d_in[0];
    const float* features = (const float*)d_in[1];
    const float* W_down   = (const float*)d_in[2];
    const float* b_down   = (const float*)d_in[3];
    const float* W_edge   = (const float*)d_in[4];
    const float* b_edge   = (const float*)d_in[5];
    const float* gamma    = (const float*)d_in[6];
    const float* beta     = (const float*)d_in[7];
    const float* mean     = (const float*)d_in[8];
    const float* var      = (const float*)d_in[9];
    const float* W_up     = (const float*)d_in[10];
    const float* b_up     = (const float*)d_in[11];
    float* out = (float*)d_out;

    const int SMEM_DYN = 98304;
    static bool attr_done = false;
    if (!attr_done) {
        cudaFuncSetAttribute(gemm_f16_2t<0>, cudaFuncAttributeMaxDynamicSharedMemorySize, SMEM_DYN);
        cudaFuncSetAttribute(gemm_f16_2t<1>, cudaFuncAttributeMaxDynamicSharedMemorySize, SMEM_DYN);
        cudaFuncSetAttribute(gemm_f16_2t<2>, cudaFuncAttributeMaxDynamicSharedMemorySize, SMEM_DYN);
        attr_done = true;
    }

    void *p_fa, *p_wdh, *p_wdl, *p_wch, *p_wcl, *p_wuh, *p_wul;
    void *p_fl, *p_ab, *p_loc;
    cudaGetSymbolAddress(&p_fa,  g_fa);
    cudaGetSymbolAddress(&p_wdh, g_wdT_h); cudaGetSymbolAddress(&p_wdl, g_wdT_l);
    cudaGetSymbolAddress(&p_wch, g_wcT_h); cudaGetSymbolAddress(&p_wcl, g_wcT_l);
    cudaGetSymbolAddress(&p_wuh, g_wuT_h); cudaGetSymbolAddress(&p_wul, g_wuT_l);
    cudaGetSymbolAddress(&p_fl,  g_fl);
    cudaGetSymbolAddress(&p_ab,  g_AB);
    cudaGetSymbolAddress(&p_loc, g_loc);

    // 1) prep + split + KNN
    prep_weights_kernel<<<(PP * DD + 255) / 256, 256>>>(
        W_down, W_edge, W_up, b_edge, gamma, beta, mean, var);
    split_features_kernel<<<(MM * DD / 4 + 255) / 256, 256>>>((const float4*)features);
    knn_kernel<<<dim3(NN / 8, BB), 256>>>(points);

    // 2) feats_low = relu(features @ W_down + b_down)  [M=16384, N=256, K=1024]
    gemm_f16_2t<1><<<dim3(PP / 128, MM / 128), 256, SMEM_DYN>>>(
        (const __half*)p_fa, (const __half*)p_wdh, (const __half*)p_wdl,
        DD, PP, (__half*)p_fl, nullptr, b_down, nullptr);

    // 3) AB = feats_low @ Wcomb                        [M, N=512, K=256]
    gemm_f16_2t<0><<<dim3(2 * PP / 128, MM / 128), 256, SMEM_DYN>>>(
        (const __half*)p_fl, (const __half*)p_wch, (const __half*)p_wcl,
        PP, 2 * PP, (__half*)p_ab, nullptr, nullptr, nullptr);

    // 4) gather + BN + relu + max over K -> local (fp16)
    edge_max_kernel<<<MM, 256>>>();

    // 5) out = features + local @ W_up + b_up          [M, N=1024, K=256]
    gemm_f16_2t<2><<<dim3(DD / 128, MM / 128), 256, SMEM_DYN>>>(
        (const __half*)p_loc, (const __half*)p_wuh, (const __half*)p_wul,
        PP, DD, nullptr, out, b_up, features);
}

// round 8
// speedup vs baseline: 1.3011x; 1.0262x over previous
#include <cuda_runtime.h>
#include <cuda_bf16.h>
#include <cuda_fp16.h>
#include <cstdint>
#include <cfloat>

#define BB   16
#define NN   1024
#define DD   1024
#define PP   256
#define KNB  16
#define MM   (BB * NN)     // 16384

// ===================== helpers ==============================================
__device__ __forceinline__ uint32_t smem_u32(const void* p) {
    uint32_t a;
    asm("{ .reg .u64 t; cvta.to.shared.u64 t, %1; cvt.u32.u64 %0, t; }" : "=r"(a) : "l"(p));
    return a;
}
__device__ __forceinline__ uint64_t cvta_g(const void* p) {
    uint64_t r; asm("cvta.to.global.u64 %0, %1;" : "=l"(r) : "l"(p)); return r;
}
#define SMEM_SWIZZLE_128B(off) ((off) ^ (((off) >> 3) & 0x70))

#define CP_ASYNC16(dst, src) \
    asm volatile("cp.async.cg.shared.global [%0], [%1], 16;" :: "r"(dst), "l"(src) : "memory")
#define CP_COMMIT() asm volatile("cp.async.commit_group;" ::: "memory")
#define CP_WAIT(n)  asm volatile("cp.async.wait_group %0;" :: "n"(n) : "memory")

#define LDSM_X4(r0, r1, r2, r3, addr) \
    asm volatile("ldmatrix.sync.aligned.m8n8.x4.shared.b16 {%0,%1,%2,%3}, [%4];" \
                 : "=r"(r0), "=r"(r1), "=r"(r2), "=r"(r3) : "r"(addr))

#define MMA_F16(d, a, b) \
    asm volatile("mma.sync.aligned.m16n8k16.row.col.f32.f16.f16.f32 " \
                 "{%0,%1,%2,%3}, {%4,%5,%6,%7}, {%8,%9}, {%0,%1,%2,%3};" \
                 : "+f"((d)[0]), "+f"((d)[1]), "+f"((d)[2]), "+f"((d)[3]) \
                 : "r"((a)[0]), "r"((a)[1]), "r"((a)[2]), "r"((a)[3]), \
                   "r"((b)[0]), "r"((b)[1]))

// ===================== scratch ==============================================
__device__ __half g_fa[(size_t)MM * DD];      // features fp16 [M][1024]
__device__ __half g_wdT_h[PP * DD];           // W_down^T hi/lo fp16 [256][1024]
__device__ __half g_wdT_l[PP * DD];
__device__ __half g_wcT_h[2 * PP * PP];       // Wcomb^T hi/lo fp16 [512][256]
__device__ __half g_wcT_l[2 * PP * PP];
__device__ __half g_wuT_h[DD * PP];           // W_up^T hi/lo fp16 [1024][256]
__device__ __half g_wuT_l[DD * PP];
__device__ __half g_fl[(size_t)MM * PP];      // feats_low fp16 [M][256]
__device__ __half g_AB[(size_t)MM * 2 * PP];  // fp16 [M][0:256]=A',[256:512]=Bv
__device__ __half g_loc[(size_t)MM * PP];     // local fp16 [M][256]
__device__ int    g_idx[MM * KNB];
__device__ float  g_s[PP];
__device__ float  g_t[PP];

__device__ __forceinline__ void split_hf(float v, __half& h, __half& l) {
    h = __float2half_rn(v);
    l = __float2half_rn(v - __half2float(h));
}

// ===================== prep kernels =========================================
__global__ void split_features_kernel(const float4* __restrict__ f) {
    int i = blockIdx.x * blockDim.x + threadIdx.x;
    if (i >= MM * DD / 4) return;
    float4 v = f[i];
    __half hh[4];
    hh[0] = __float2half_rn(v.x);
    hh[1] = __float2half_rn(v.y);
    hh[2] = __float2half_rn(v.z);
    hh[3] = __float2half_rn(v.w);
    *(uint2*)(g_fa + 4 * (size_t)i) = *(uint2*)hh;
}

__global__ void prep_weights_kernel(const float* __restrict__ W_down,
                                    const float* __restrict__ W_edge,
                                    const float* __restrict__ W_up,
                                    const float* __restrict__ b_edge,
                                    const float* __restrict__ gamma,
                                    const float* __restrict__ beta,
                                    const float* __restrict__ mean,
                                    const float* __restrict__ var) {
    int t = blockIdx.x * blockDim.x + threadIdx.x;
    if (t < PP * DD) {
        float v = W_down[(size_t)(t & 1023) * PP + (t >> 10)];
        split_hf(v, g_wdT_h[t], g_wdT_l[t]);
    }
    if (t < DD * PP) {
        float v = W_up[(size_t)(t & 255) * DD + (t >> 8)];
        split_hf(v, g_wuT_h[t], g_wuT_l[t]);
    }
    if (t < 2 * PP * PP) {
        int p = t >> 8, f = t & 255;
        float v = (p < PP) ? (W_edge[f * PP + p] - W_edge[(f + PP) * PP + p])
                           : W_edge[(f + PP) * PP + (p - PP)];
        split_hf(v, g_wcT_h[t], g_wcT_l[t]);
    }
    if (t < PP) {
        float rs = rsqrtf(var[t] + 1e-5f);
        float sv = gamma[t] * rs;
        g_s[t] = sv;
        g_t[t] = beta[t] - mean[t] * sv + sv * b_edge[t];
    }
}

// ===================== KNN: warp-per-point, 32-bit exact extraction =========
__global__ __launch_bounds__(256) void knn_kernel(const float* __restrict__ pts) {
    const int b    = blockIdx.y;
    const int warp = threadIdx.x >> 5;
    const int lane = threadIdx.x & 31;
    const int n    = blockIdx.x * 8 + warp;

    __shared__ float4 sp[NN];     // 16 KB: (x, y, z, |p|^2)
    for (int m = threadIdx.x; m < NN; m += 256) {
        float x = pts[((size_t)b * NN + m) * 3 + 0];
        float y = pts[((size_t)b * NN + m) * 3 + 1];
        float z = pts[((size_t)b * NN + m) * 3 + 2];
        sp[m] = make_float4(x, y, z, fmaf(x, x, fmaf(y, y, z * z)));
    }
    __syncthreads();

    const float4 P = sp[n];
    const float BIGF = 3.0e38f;

    float d[32];
    float pmin = BIGF;
#pragma unroll
    for (int j = 0; j < 32; ++j) {
        float4 q = sp[j * 32 + lane];
        float dot = fmaf(P.x, q.x, fmaf(P.y, q.y, P.z * q.z));
        d[j] = fmaf(-2.0f, dot, P.w + q.w);
        pmin = fminf(pmin, d[j]);
    }

    const int base = ((b << 10) + n) * KNB;

#pragma unroll
    for (int r = 0; r < KNB; ++r) {
        float g = pmin;
#pragma unroll
        for (int s = 16; s; s >>= 1)
            g = fminf(g, __shfl_xor_sync(0xffffffffu, g, s));

        int jm = 99;
#pragma unroll
        for (int j = 31; j >= 0; --j)
            jm = (d[j] == g) ? j : jm;

        int mc = (pmin == g) ? (jm * 32 + lane) : 0x7FFFFFFF;
#pragma unroll
        for (int s = 16; s; s >>= 1) {
            int o = __shfl_xor_sync(0xffffffffu, mc, s);
            mc = o < mc ? o : mc;
        }
        if (lane == 0) g_idx[base + r] = mc;
        if (r == KNB - 1) break;

        const int jkill = (lane == (mc & 31)) ? (mc >> 5) : 64;
        pmin = BIGF;
#pragma unroll
        for (int j = 0; j < 32; ++j) {
            d[j] = (j == jkill) ? BIGF : d[j];
            pmin = fminf(pmin, d[j]);
        }
    }
}

// ===================== edge gather + BN + relu + max ========================
__global__ __launch_bounds__(256) void edge_max_kernel() {
    const int bn = blockIdx.x;
    const int p  = threadIdx.x;
    const int b  = bn >> 10;

    __shared__ int sidx[KNB];
    if (p < KNB) sidx[p] = g_idx[bn * KNB + p];
    __syncthreads();

    const float a  = __half2float(g_AB[(size_t)bn * 512 + p]);
    const float sp = g_s[p];
    const float tp = g_t[p];

    float acc = 0.0f;
#pragma unroll
    for (int k = 0; k < KNB; ++k) {
        float v = __half2float(g_AB[(size_t)((b << 10) + sidx[k]) * 512 + PP + p]);
        float h = fmaf(sp, a + v, tp);
        acc = fmaxf(acc, h);
    }
    g_loc[(size_t)bn * PP + p] = __float2half_rn(acc);
}

// ===================== GEMM fp16 2-term, 2-stage, k-chunk 64 ================
// C = A(fp16) @ (Bh+Bl)^T ; B stored [N][K].
// EPI 0: store fp16 ; EPI 1: relu(acc+bias) -> fp16 ; EPI 2: acc+bias+res -> f32.
template <int EPI>
__global__ void __launch_bounds__(256, 2) gemm_f16_2t(
    const __half* __restrict__ A,
    const __half* __restrict__ Bh, const __half* __restrict__ Bl,
    int K, int Nc,
    __half* __restrict__ Ch, float* __restrict__ Cf,
    const float* __restrict__ bias, const float* __restrict__ res)
{
    extern __shared__ char smraw[];
    const uint32_t smb = smem_u32(smraw);   // 2 buffers x 48KB: [A | Bh | Bl]
    const int tid = threadIdx.x, lane = tid & 31, wid = tid >> 5;
    const int warp_m = wid & 3, warp_n = wid >> 2;
    const int bm = blockIdx.y, bn = blockIdx.x;

    const uint64_t gA  = cvta_g(A  + (size_t)(bm * 128) * K);
    const uint64_t gBh = cvta_g(Bh + (size_t)(bn * 128) * K);
    const uint64_t gBl = cvta_g(Bl + (size_t)(bn * 128) * K);
    const int nk = K >> 6;

    const int grp = lane >> 3, rr = lane & 7;
    const int a_row0 = warp_m * 32 + ((grp & 1) << 3) + rr;
    const int kadd_a = (grp >> 1) << 4;
    const int b_row0 = warp_n * 64 + ((grp >> 1) << 3) + rr;
    const int kadd_b = (grp & 1) << 4;

    float acc[2][8][4];
#pragma unroll
    for (int i = 0; i < 2; ++i)
#pragma unroll
        for (int j = 0; j < 8; ++j)
#pragma unroll
            for (int c = 0; c < 4; ++c) acc[i][j][c] = 0.0f;

    auto issue = [&](int kc) {
        const uint32_t bb = (uint32_t)(kc & 1) * 49152u;
        const int kof = kc * 64;
#pragma unroll
        for (int i = 0; i < 4; ++i) {
            int idx = i * 256 + tid;
            int row = idx >> 3, g = idx & 7;
            int kel = kof + g * 8;
            uint32_t dst = SMEM_SWIZZLE_128B((uint32_t)(row * 128 + g * 16));
            size_t src = (size_t)row * K + kel;
            CP_ASYNC16(smb + bb + dst,         gA  + src * 2);
            CP_ASYNC16(smb + bb + 16384 + dst, gBh + src * 2);
            CP_ASYNC16(smb + bb + 32768 + dst, gBl + src * 2);
        }
    };

    issue(0); CP_COMMIT();

    for (int kc = 0; kc < nk; ++kc) {
        if (kc + 1 < nk) issue(kc + 1);
        CP_COMMIT();
        CP_WAIT(1);
        __syncthreads();

        const uint32_t bufA  = smb + (uint32_t)(kc & 1) * 49152u;
        const uint32_t bufBh = bufA + 16384;
        const uint32_t bufBl = bufA + 32768;

#pragma unroll
        for (int s = 0; s < 4; ++s) {
            uint32_t af[2][4];
#pragma unroll
            for (int mt = 0; mt < 2; ++mt) {
                int row = a_row0 + mt * 16;
                uint32_t rb = bufA + row * 128;
                uint32_t xr = (row & 7) << 4;
                LDSM_X4(af[mt][0], af[mt][1], af[mt][2], af[mt][3],
                        rb + (((uint32_t)(s * 32 + kadd_a)) ^ xr));
            }
#pragma unroll
            for (int jg = 0; jg < 2; ++jg) {
                uint32_t bh[4][2], bl[4][2];
#pragma unroll
                for (int p = 0; p < 2; ++p) {
                    int row = b_row0 + jg * 32 + p * 16;
                    uint32_t xr = (row & 7) << 4;
                    uint32_t by = (uint32_t)(s * 32 + kadd_b);
                    LDSM_X4(bh[2 * p][0], bh[2 * p][1], bh[2 * p + 1][0], bh[2 * p + 1][1],
                            bufBh + row * 128 + (by ^ xr));
                    LDSM_X4(bl[2 * p][0], bl[2 * p][1], bl[2 * p + 1][0], bl[2 * p + 1][1],
                            bufBl + row * 128 + (by ^ xr));
                }
#pragma unroll
                for (int mt = 0; mt < 2; ++mt)
#pragma unroll
                    for (int j = 0; j < 4; ++j) {
                        float* d = acc[mt][jg * 4 + j];
                        MMA_F16(d, af[mt], bh[j]);
                        MMA_F16(d, af[mt], bl[j]);
                    }
            }
        }
        __syncthreads();
    }

#pragma unroll
    for (int mt = 0; mt < 2; ++mt)
#pragma unroll
        for (int half = 0; half < 2; ++half) {
            size_t row = (size_t)bm * 128 + warp_m * 32 + mt * 16 + half * 8 + (lane >> 2);
#pragma unroll
            for (int j = 0; j < 8; ++j) {
                int col = bn * 128 + warp_n * 64 + j * 8 + 2 * (lane & 3);
                float v0 = acc[mt][j][half * 2 + 0];
                float v1 = acc[mt][j][half * 2 + 1];
                if (EPI == 0) {
                    __half2 hv; hv.x = __float2half_rn(v0); hv.y = __float2half_rn(v1);
                    *(__half2*)(Ch + row * Nc + col) = hv;
                } else if (EPI == 1) {
                    v0 = fmaxf(v0 + bias[col], 0.0f);
                    v1 = fmaxf(v1 + bias[col + 1], 0.0f);
                    __half2 hv; hv.x = __float2half_rn(v0); hv.y = __float2half_rn(v1);
                    *(__half2*)(Ch + row * Nc + col) = hv;
                } else {
                    float2 r = *(const float2*)(res + row * Nc + col);
                    *(float2*)(Cf + row * Nc + col) =
                        make_float2(v0 + bias[col] + r.x, v1 + bias[col + 1] + r.y);
                }
            }
        }
}

// ===================== launch ===============================================
extern "C" void kernel_launch(void* const* d_in, const int* in_sizes, int n_in,
                              void* d_out, int out_size)
{
    const float* points   = (const float*)d_in[0];
    const float* features = (const float*)d_in[1];
    const float* W_down   = (const float*)d_in[2];
    const float* b_down   = (const float*)d_in[3];
    const float* W_edge   = (const float*)d_in[4];
    const float* b_edge   = (const float*)d_in[5];
    const float* gamma    = (const float*)d_in[6];
    const float* beta     = (const float*)d_in[7];
    const float* mean     = (const float*)d_in[8];
    const float* var      = (const float*)d_in[9];
    const float* W_up     = (const float*)d_in[10];
    const float* b_up     = (const float*)d_in[11];
    float* out = (float*)d_out;

    const int SMEM_DYN = 98304;
    static bool init_done = false;
    static cudaStream_t s2 = nullptr;
    static cudaEvent_t ev_fork = nullptr, ev_join = nullptr;
    if (!init_done) {
        cudaFuncSetAttribute(gemm_f16_2t<0>, cudaFuncAttributeMaxDynamicSharedMemorySize, SMEM_DYN);
        cudaFuncSetAttribute(gemm_f16_2t<1>, cudaFuncAttributeMaxDynamicSharedMemorySize, SMEM_DYN);
        cudaFuncSetAttribute(gemm_f16_2t<2>, cudaFuncAttributeMaxDynamicSharedMemorySize, SMEM_DYN);
        cudaStreamCreateWithFlags(&s2, cudaStreamNonBlocking);
        cudaEventCreateWithFlags(&ev_fork, cudaEventDisableTiming);
        cudaEventCreateWithFlags(&ev_join, cudaEventDisableTiming);
        init_done = true;
    }

    void *p_fa, *p_wdh, *p_wdl, *p_wch, *p_wcl, *p_wuh, *p_wul;
    void *p_fl, *p_ab, *p_loc;
    cudaGetSymbolAddress(&p_fa,  g_fa);
    cudaGetSymbolAddress(&p_wdh, g_wdT_h); cudaGetSymbolAddress(&p_wdl, g_wdT_l);
    cudaGetSymbolAddress(&p_wch, g_wcT_h); cudaGetSymbolAddress(&p_wcl, g_wcT_l);
    cudaGetSymbolAddress(&p_wuh, g_wuT_h); cudaGetSymbolAddress(&p_wul, g_wuT_l);
    cudaGetSymbolAddress(&p_fl,  g_fl);
    cudaGetSymbolAddress(&p_ab,  g_AB);
    cudaGetSymbolAddress(&p_loc, g_loc);

    // ---- fork: KNN runs on s2, concurrent with the feature/GEMM chain ----
    cudaEventRecord(ev_fork, 0);
    cudaStreamWaitEvent(s2, ev_fork, 0);
    knn_kernel<<<dim3(NN / 8, BB), 256, 0, s2>>>(points);
    cudaEventRecord(ev_join, s2);

    // ---- main stream: prep + split + GEMM1 + GEMM2 ----
    prep_weights_kernel<<<(PP * DD + 255) / 256, 256>>>(
        W_down, W_edge, W_up, b_edge, gamma, beta, mean, var);
    split_features_kernel<<<(MM * DD / 4 + 255) / 256, 256>>>((const float4*)features);

    // feats_low = relu(features @ W_down + b_down)  [M=16384, N=256, K=1024]
    gemm_f16_2t<1><<<dim3(PP / 128, MM / 128), 256, SMEM_DYN>>>(
        (const __half*)p_fa, (const __half*)p_wdh, (const __half*)p_wdl,
        DD, PP, (__half*)p_fl, nullptr, b_down, nullptr);

    // AB = feats_low @ Wcomb                        [M, N=512, K=256]
    gemm_f16_2t<0><<<dim3(2 * PP / 128, MM / 128), 256, SMEM_DYN>>>(
        (const __half*)p_fl, (const __half*)p_wch, (const __half*)p_wcl,
        PP, 2 * PP, (__half*)p_ab, nullptr, nullptr, nullptr);

    // ---- join: edge_max needs both KNN (s2) and GEMM2 (main) ----
    cudaStreamWaitEvent(0, ev_join, 0);
    edge_max_kernel<<<MM, 256>>>();

    // out = features + local @ W_up + b_up          [M, N=1024, K=256]
    gemm_f16_2t<2><<<dim3(DD / 128, MM / 128), 256, SMEM_DYN>>>(
        (const __half*)p_loc, (const __half*)p_wuh, (const __half*)p_wul,
        PP, DD, nullptr, out, b_up, features);
}

// round 10
// speedup vs baseline: 1.3658x; 1.0497x over previous
#include <cuda_runtime.h>
#include <cuda_bf16.h>
#include <cuda_fp16.h>
#include <cstdint>
#include <cfloat>

#define BB   16
#define NN   1024
#define DD   1024
#define PP   256
#define KNB  16
#define MM   (BB * NN)     // 16384

// ===================== helpers ==============================================
__device__ __forceinline__ uint32_t smem_u32(const void* p) {
    uint32_t a;
    asm("{ .reg .u64 t; cvta.to.shared.u64 t, %1; cvt.u32.u64 %0, t; }" : "=r"(a) : "l"(p));
    return a;
}
__device__ __forceinline__ uint64_t cvta_g(const void* p) {
    uint64_t r; asm("cvta.to.global.u64 %0, %1;" : "=l"(r) : "l"(p)); return r;
}
#define SMEM_SWIZZLE_128B(off) ((off) ^ (((off) >> 3) & 0x70))

#define CP_ASYNC16(dst, src) \
    asm volatile("cp.async.cg.shared.global [%0], [%1], 16;" :: "r"(dst), "l"(src) : "memory")
#define CP_COMMIT() asm volatile("cp.async.commit_group;" ::: "memory")
#define CP_WAIT(n)  asm volatile("cp.async.wait_group %0;" :: "n"(n) : "memory")

#define LDSM_X4(r0, r1, r2, r3, addr) \
    asm volatile("ldmatrix.sync.aligned.m8n8.x4.shared.b16 {%0,%1,%2,%3}, [%4];" \
                 : "=r"(r0), "=r"(r1), "=r"(r2), "=r"(r3) : "r"(addr))

#define MMA_F16(d, a, b) \
    asm volatile("mma.sync.aligned.m16n8k16.row.col.f32.f16.f16.f32 " \
                 "{%0,%1,%2,%3}, {%4,%5,%6,%7}, {%8,%9}, {%0,%1,%2,%3};" \
                 : "+f"((d)[0]), "+f"((d)[1]), "+f"((d)[2]), "+f"((d)[3]) \
                 : "r"((a)[0]), "r"((a)[1]), "r"((a)[2]), "r"((a)[3]), \
                   "r"((b)[0]), "r"((b)[1]))

// ===================== scratch ==============================================
__device__ __half g_fa[(size_t)MM * DD];      // features fp16 [M][1024]
__device__ __half g_wdT_h[PP * DD];           // W_down^T hi/lo fp16 [256][1024]
__device__ __half g_wdT_l[PP * DD];
__device__ __half g_wcT_h[2 * PP * PP];       // s-scaled Wcomb^T hi/lo [512][256]
__device__ __half g_wcT_l[2 * PP * PP];
__device__ __half g_wuT_h[DD * PP];           // W_up^T hi/lo fp16 [1024][256]
__device__ __half g_wuT_l[DD * PP];
__device__ __half g_fl[(size_t)MM * PP];      // feats_low fp16 [M][256]
__device__ __half g_AB[(size_t)MM * 2 * PP];  // fp16 [M][0:256]=As,[256:512]=Vs
__device__ __half g_loc[(size_t)MM * PP];     // local fp16 [M][256]
__device__ int    g_idx[MM * KNB];
__device__ float  g_tf[2 * PP];               // epilogue bias: t for cols<256, 0 else

__device__ __forceinline__ void split_hf(float v, __half& h, __half& l) {
    h = __float2half_rn(v);
    l = __float2half_rn(v - __half2float(h));
}

// ===================== prep kernels =========================================
__global__ void split_features_kernel(const float4* __restrict__ f) {
    int i = blockIdx.x * blockDim.x + threadIdx.x;
    if (i >= MM * DD / 4) return;
    float4 v = f[i];
    __half hh[4];
    hh[0] = __float2half_rn(v.x);
    hh[1] = __float2half_rn(v.y);
    hh[2] = __float2half_rn(v.z);
    hh[3] = __float2half_rn(v.w);
    *(uint2*)(g_fa + 4 * (size_t)i) = *(uint2*)hh;
}

__global__ void prep_weights_kernel(const float* __restrict__ W_down,
                                    const float* __restrict__ W_edge,
                                    const float* __restrict__ W_up,
                                    const float* __restrict__ b_edge,
                                    const float* __restrict__ gamma,
                                    const float* __restrict__ beta,
                                    const float* __restrict__ mean,
                                    const float* __restrict__ var) {
    int t = blockIdx.x * blockDim.x + threadIdx.x;
    if (t < PP * DD) {
        float v = W_down[(size_t)(t & 1023) * PP + (t >> 10)];
        split_hf(v, g_wdT_h[t], g_wdT_l[t]);
    }
    if (t < DD * PP) {
        float v = W_up[(size_t)(t & 255) * DD + (t >> 8)];
        split_hf(v, g_wuT_h[t], g_wuT_l[t]);
    }
    if (t < 2 * PP * PP) {  // s-scaled Wcomb^T: row p (out col), col f
        int p = t >> 8, f = t & 255;
        int pc = p & 255;
        float sv = gamma[pc] * rsqrtf(var[pc] + 1e-5f);
        float v = (p < PP) ? (W_edge[f * PP + p] - W_edge[(f + PP) * PP + p])
                           : W_edge[(f + PP) * PP + (p - PP)];
        split_hf(sv * v, g_wcT_h[t], g_wcT_l[t]);
    }
    if (t < 2 * PP) {
        if (t < PP) {
            float rs = rsqrtf(var[t] + 1e-5f);
            float sv = gamma[t] * rs;
            g_tf[t] = beta[t] - mean[t] * sv + sv * b_edge[t];
        } else {
            g_tf[t] = 0.0f;
        }
    }
}

// ===================== KNN: warp-per-point, 32-bit exact extraction =========
// Lane holds 32 candidate distances (m = j*32 + lane) as plain floats (exact).
// 16 rounds: fminf warp-reduce finds exact min value; owner identified by
// exact compare; ties broken by integer min over m (= top_k's smallest-index
// rule); single winner invalidates its copy.
__global__ __launch_bounds__(256) void knn_kernel(const float* __restrict__ pts) {
    const int b    = blockIdx.y;
    const int warp = threadIdx.x >> 5;
    const int lane = threadIdx.x & 31;
    const int n    = blockIdx.x * 8 + warp;

    __shared__ float4 sp[NN];     // 16 KB: (x, y, z, |p|^2)
    for (int m = threadIdx.x; m < NN; m += 256) {
        float x = pts[((size_t)b * NN + m) * 3 + 0];
        float y = pts[((size_t)b * NN + m) * 3 + 1];
        float z = pts[((size_t)b * NN + m) * 3 + 2];
        sp[m] = make_float4(x, y, z, fmaf(x, x, fmaf(y, y, z * z)));
    }
    __syncthreads();

    const float4 P = sp[n];
    const float BIGF = 3.0e38f;

    float d[32];
    float pmin = BIGF;
#pragma unroll
    for (int j = 0; j < 32; ++j) {
        float4 q = sp[j * 32 + lane];
        float dot = fmaf(P.x, q.x, fmaf(P.y, q.y, P.z * q.z));
        d[j] = fmaf(-2.0f, dot, P.w + q.w);
        pmin = fminf(pmin, d[j]);
    }

    const int base = ((b << 10) + n) * KNB;

#pragma unroll
    for (int r = 0; r < KNB; ++r) {
        float g = pmin;
#pragma unroll
        for (int s = 16; s; s >>= 1)
            g = fminf(g, __shfl_xor_sync(0xffffffffu, g, s));

        int jm = 99;
#pragma unroll
        for (int j = 31; j >= 0; --j)
            jm = (d[j] == g) ? j : jm;

        int mc = (pmin == g) ? (jm * 32 + lane) : 0x7FFFFFFF;
#pragma unroll
        for (int s = 16; s; s >>= 1) {
            int o = __shfl_xor_sync(0xffffffffu, mc, s);
            mc = o < mc ? o : mc;
        }
        if (lane == 0) g_idx[base + r] = mc;
        if (r == KNB - 1) break;

        const int jkill = (lane == (mc & 31)) ? (mc >> 5) : 64;
        pmin = BIGF;
#pragma unroll
        for (int j = 0; j < 32; ++j) {
            d[j] = (j == jkill) ? BIGF : d[j];
            pmin = fminf(pmin, d[j]);
        }
    }
}

// ===================== edge gather + max (BN folded upstream) ===============
// h = As[bn,p] + Vs[nb,p] ; local = relu(max_k h) ; half2-vectorized.
__global__ __launch_bounds__(128) void edge_max_kernel() {
    const int bn = blockIdx.x;
    const int t  = threadIdx.x;        // 0..127 -> cols 2t, 2t+1
    const int b  = bn >> 10;

    __shared__ int sidx[KNB];
    if (t < KNB) sidx[t] = g_idx[bn * KNB + t];
    __syncthreads();

    const __half2* AB2 = (const __half2*)g_AB;   // row stride 256 half2
    float2 a = __half22float2(AB2[(size_t)bn * 256 + t]);

    float acc0 = 0.0f, acc1 = 0.0f;   // relu(max) == max with 0 floor
#pragma unroll
    for (int k = 0; k < KNB; ++k) {
        float2 v = __half22float2(AB2[(size_t)((b << 10) + sidx[k]) * 256 + 128 + t]);
        acc0 = fmaxf(acc0, a.x + v.x);
        acc1 = fmaxf(acc1, a.y + v.y);
    }
    ((__half2*)g_loc)[(size_t)bn * 128 + t] = __floats2half2_rn(acc0, acc1);
}

// ===================== GEMM fp16 2-term, 2-stage, k-chunk 64 ================
// C = A(fp16) @ (Bh+Bl)^T ; B stored [N][K].
// EPI 0: store fp16 ; EPI 1: relu(acc+bias)->fp16 ; EPI 2: acc+bias+res->f32 ;
// EPI 3: (acc+bias)->fp16.
template <int EPI>
__global__ void __launch_bounds__(256, 2) gemm_f16_2t(
    const __half* __restrict__ A,
    const __half* __restrict__ Bh, const __half* __restrict__ Bl,
    int K, int Nc,
    __half* __restrict__ Ch, float* __restrict__ Cf,
    const float* __restrict__ bias, const float* __restrict__ res)
{
    extern __shared__ char smraw[];
    const uint32_t smb = smem_u32(smraw);   // 2 buffers x 48KB: [A | Bh | Bl]
    const int tid = threadIdx.x, lane = tid & 31, wid = tid >> 5;
    const int warp_m = wid & 3, warp_n = wid >> 2;
    const int bm = blockIdx.y, bn = blockIdx.x;

    const uint64_t gA  = cvta_g(A  + (size_t)(bm * 128) * K);
    const uint64_t gBh = cvta_g(Bh + (size_t)(bn * 128) * K);
    const uint64_t gBl = cvta_g(Bl + (size_t)(bn * 128) * K);
    const int nk = K >> 6;

    const int grp = lane >> 3, rr = lane & 7;
    const int a_row0 = warp_m * 32 + ((grp & 1) << 3) + rr;
    const int kadd_a = (grp >> 1) << 4;
    const int b_row0 = warp_n * 64 + ((grp >> 1) << 3) + rr;
    const int kadd_b = (grp & 1) << 4;

    float acc[2][8][4];
#pragma unroll
    for (int i = 0; i < 2; ++i)
#pragma unroll
        for (int j = 0; j < 8; ++j)
#pragma unroll
            for (int c = 0; c < 4; ++c) acc[i][j][c] = 0.0f;

    auto issue = [&](int kc) {
        const uint32_t bb = (uint32_t)(kc & 1) * 49152u;
        const int kof = kc * 64;
#pragma unroll
        for (int i = 0; i < 4; ++i) {
            int idx = i * 256 + tid;
            int row = idx >> 3, g = idx & 7;
            int kel = kof + g * 8;
            uint32_t dst = SMEM_SWIZZLE_128B((uint32_t)(row * 128 + g * 16));
            size_t src = (size_t)row * K + kel;
            CP_ASYNC16(smb + bb + dst,         gA  + src * 2);
            CP_ASYNC16(smb + bb + 16384 + dst, gBh + src * 2);
            CP_ASYNC16(smb + bb + 32768 + dst, gBl + src * 2);
        }
    };

    issue(0); CP_COMMIT();

    for (int kc = 0; kc < nk; ++kc) {
        if (kc + 1 < nk) issue(kc + 1);
        CP_COMMIT();
        CP_WAIT(1);
        __syncthreads();

        const uint32_t bufA  = smb + (uint32_t)(kc & 1) * 49152u;
        const uint32_t bufBh = bufA + 16384;
        const uint32_t bufBl = bufA + 32768;

#pragma unroll
        for (int s = 0; s < 4; ++s) {
            uint32_t af[2][4];
#pragma unroll
            for (int mt = 0; mt < 2; ++mt) {
                int row = a_row0 + mt * 16;
                uint32_t rb = bufA + row * 128;
                uint32_t xr = (row & 7) << 4;
                LDSM_X4(af[mt][0], af[mt][1], af[mt][2], af[mt][3],
                        rb + (((uint32_t)(s * 32 + kadd_a)) ^ xr));
            }
#pragma unroll
            for (int jg = 0; jg < 2; ++jg) {
                uint32_t bh[4][2], bl[4][2];
#pragma unroll
                for (int p = 0; p < 2; ++p) {
                    int row = b_row0 + jg * 32 + p * 16;
                    uint32_t xr = (row & 7) << 4;
                    uint32_t by = (uint32_t)(s * 32 + kadd_b);
                    LDSM_X4(bh[2 * p][0], bh[2 * p][1], bh[2 * p + 1][0], bh[2 * p + 1][1],
                            bufBh + row * 128 + (by ^ xr));
                    LDSM_X4(bl[2 * p][0], bl[2 * p][1], bl[2 * p + 1][0], bl[2 * p + 1][1],
                            bufBl + row * 128 + (by ^ xr));
                }
#pragma unroll
                for (int mt = 0; mt < 2; ++mt)
#pragma unroll
                    for (int j = 0; j < 4; ++j) {
                        float* d = acc[mt][jg * 4 + j];
                        MMA_F16(d, af[mt], bh[j]);
                        MMA_F16(d, af[mt], bl[j]);
                    }
            }
        }
        __syncthreads();
    }

#pragma unroll
    for (int mt = 0; mt < 2; ++mt)
#pragma unroll
        for (int half = 0; half < 2; ++half) {
            size_t row = (size_t)bm * 128 + warp_m * 32 + mt * 16 + half * 8 + (lane >> 2);
#pragma unroll
            for (int j = 0; j < 8; ++j) {
                int col = bn * 128 + warp_n * 64 + j * 8 + 2 * (lane & 3);
                float v0 = acc[mt][j][half * 2 + 0];
                float v1 = acc[mt][j][half * 2 + 1];
                if (EPI == 0) {
                    __half2 hv; hv.x = __float2half_rn(v0); hv.y = __float2half_rn(v1);
                    *(__half2*)(Ch + row * Nc + col) = hv;
                } else if (EPI == 1) {
                    v0 = fmaxf(v0 + bias[col], 0.0f);
                    v1 = fmaxf(v1 + bias[col + 1], 0.0f);
                    __half2 hv; hv.x = __float2half_rn(v0); hv.y = __float2half_rn(v1);
                    *(__half2*)(Ch + row * Nc + col) = hv;
                } else if (EPI == 3) {
                    v0 = v0 + bias[col];
                    v1 = v1 + bias[col + 1];
                    __half2 hv; hv.x = __float2half_rn(v0); hv.y = __float2half_rn(v1);
                    *(__half2*)(Ch + row * Nc + col) = hv;
                } else {
                    float2 r = *(const float2*)(res + row * Nc + col);
                    *(float2*)(Cf + row * Nc + col) =
                        make_float2(v0 + bias[col] + r.x, v1 + bias[col + 1] + r.y);
                }
            }
        }
}

// ===================== launch ===============================================
extern "C" void kernel_launch(void* const* d_in, const int* in_sizes, int n_in,
                              void* d_out, int out_size)
{
    const float* points   = (const float*)d_in[0];
    const float* features = (const float*)d_in[1];
    const float* W_down   = (const float*)d_in[2];
    const float* b_down   = (const float*)d_in[3];
    const float* W_edge   = (const float*)d_in[4];
    const float* b_edge   = (const float*)d_in[5];
    const float* gamma    = (const float*)d_in[6];
    const float* beta     = (const float*)d_in[7];
    const float* mean     = (const float*)d_in[8];
    const float* var      = (const float*)d_in[9];
    const float* W_up     = (const float*)d_in[10];
    const float* b_up     = (const float*)d_in[11];
    float* out = (float*)d_out;

    const int SMEM_DYN = 98304;
    static bool init_done = false;
    static cudaStream_t s2 = nullptr;
    static cudaEvent_t ev_fork = nullptr, ev_join = nullptr;
    if (!init_done) {
        cudaFuncSetAttribute(gemm_f16_2t<1>, cudaFuncAttributeMaxDynamicSharedMemorySize, SMEM_DYN);
        cudaFuncSetAttribute(gemm_f16_2t<2>, cudaFuncAttributeMaxDynamicSharedMemorySize, SMEM_DYN);
        cudaFuncSetAttribute(gemm_f16_2t<3>, cudaFuncAttributeMaxDynamicSharedMemorySize, SMEM_DYN);
        cudaStreamCreateWithFlags(&s2, cudaStreamNonBlocking);
        cudaEventCreateWithFlags(&ev_fork, cudaEventDisableTiming);
        cudaEventCreateWithFlags(&ev_join, cudaEventDisableTiming);
        init_done = true;
    }

    void *p_fa, *p_wdh, *p_wdl, *p_wch, *p_wcl, *p_wuh, *p_wul;
    void *p_fl, *p_ab, *p_loc, *p_tf;
    cudaGetSymbolAddress(&p_fa,  g_fa);
    cudaGetSymbolAddress(&p_wdh, g_wdT_h); cudaGetSymbolAddress(&p_wdl, g_wdT_l);
    cudaGetSymbolAddress(&p_wch, g_wcT_h); cudaGetSymbolAddress(&p_wcl, g_wcT_l);
    cudaGetSymbolAddress(&p_wuh, g_wuT_h); cudaGetSymbolAddress(&p_wul, g_wuT_l);
    cudaGetSymbolAddress(&p_fl,  g_fl);
    cudaGetSymbolAddress(&p_ab,  g_AB);
    cudaGetSymbolAddress(&p_loc, g_loc);
    cudaGetSymbolAddress(&p_tf,  g_tf);

    // ---- fork: KNN runs on s2, concurrent with the feature/GEMM chain ----
    cudaEventRecord(ev_fork, 0);
    cudaStreamWaitEvent(s2, ev_fork, 0);
    knn_kernel<<<dim3(NN / 8, BB), 256, 0, s2>>>(points);
    cudaEventRecord(ev_join, s2);

    // ---- main stream: prep + split + GEMM1 + GEMM2 ----
    prep_weights_kernel<<<(PP * DD + 255) / 256, 256>>>(
        W_down, W_edge, W_up, b_edge, gamma, beta, mean, var);
    split_features_kernel<<<(MM * DD / 4 + 255) / 256, 256>>>((const float4*)features);

    // feats_low = relu(features @ W_down + b_down)  [M=16384, N=256, K=1024]
    gemm_f16_2t<1><<<dim3(PP / 128, MM / 128), 256, SMEM_DYN>>>(
        (const __half*)p_fa, (const __half*)p_wdh, (const __half*)p_wdl,
        DD, PP, (__half*)p_fl, nullptr, b_down, nullptr);

    // AB = feats_low @ (s-scaled Wcomb) + tf        [M, N=512, K=256]
    gemm_f16_2t<3><<<dim3(2 * PP / 128, MM / 128), 256, SMEM_DYN>>>(
        (const __half*)p_fl, (const __half*)p_wch, (const __half*)p_wcl,
        PP, 2 * PP, (__half*)p_ab, nullptr, (const float*)p_tf, nullptr);

    // ---- join: edge_max needs both KNN (s2) and GEMM2 (main) ----
    cudaStreamWaitEvent(0, ev_join, 0);
    edge_max_kernel<<<MM, 128>>>();

    // out = features + local @ W_up + b_up          [M, N=1024, K=256]
    gemm_f16_2t<2><<<dim3(DD / 128, MM / 128), 256, SMEM_DYN>>>(
        (const __half*)p_loc, (const __half*)p_wuh, (const __half*)p_wul,
        PP, DD, nullptr, out, b_up, features);
}

// round 11
// speedup vs baseline: 1.5042x; 1.1014x over previous
#include <cuda_runtime.h>
#include <cuda_bf16.h>
#include <cuda_fp16.h>
#include <cstdint>
#include <cfloat>

#define BB   16
#define NN   1024
#define DD   1024
#define PP   256
#define KNB  16
#define MM   (BB * NN)     // 16384

// ===================== helpers ==============================================
__device__ __forceinline__ uint32_t smem_u32(const void* p) {
    uint32_t a;
    asm("{ .reg .u64 t; cvta.to.shared.u64 t, %1; cvt.u32.u64 %0, t; }" : "=r"(a) : "l"(p));
    return a;
}
__device__ __forceinline__ uint64_t cvta_g(const void* p) {
    uint64_t r; asm("cvta.to.global.u64 %0, %1;" : "=l"(r) : "l"(p)); return r;
}
#define SMEM_SWIZZLE_128B(off) ((off) ^ (((off) >> 3) & 0x70))

#define CP_ASYNC16(dst, src) \
    asm volatile("cp.async.cg.shared.global [%0], [%1], 16;" :: "r"(dst), "l"(src) : "memory")
#define CP_COMMIT() asm volatile("cp.async.commit_group;" ::: "memory")
#define CP_WAIT(n)  asm volatile("cp.async.wait_group %0;" :: "n"(n) : "memory")

#define LDSM_X4(r0, r1, r2, r3, addr) \
    asm volatile("ldmatrix.sync.aligned.m8n8.x4.shared.b16 {%0,%1,%2,%3}, [%4];" \
                 : "=r"(r0), "=r"(r1), "=r"(r2), "=r"(r3) : "r"(addr))

#define MMA_F16(d, a, b) \
    asm volatile("mma.sync.aligned.m16n8k16.row.col.f32.f16.f16.f32 " \
                 "{%0,%1,%2,%3}, {%4,%5,%6,%7}, {%8,%9}, {%0,%1,%2,%3};" \
                 : "+f"((d)[0]), "+f"((d)[1]), "+f"((d)[2]), "+f"((d)[3]) \
                 : "r"((a)[0]), "r"((a)[1]), "r"((a)[2]), "r"((a)[3]), \
                   "r"((b)[0]), "r"((b)[1]))

// ===================== scratch ==============================================
__device__ __half g_fa[(size_t)MM * DD];      // features fp16 [M][1024]
__device__ __half g_wdT[PP * DD];             // W_down^T fp16 (single) [256][1024]
__device__ __half g_wcT_h[2 * PP * PP];       // s-scaled Wcomb^T hi/lo [512][256]
__device__ __half g_wcT_l[2 * PP * PP];
__device__ __half g_wuT_h[DD * PP];           // W_up^T hi/lo fp16 [1024][256]
__device__ __half g_wuT_l[DD * PP];
__device__ __half g_fl[(size_t)MM * PP];      // feats_low fp16 [M][256]
__device__ __half g_AB[(size_t)MM * 2 * PP];  // fp16 [M][0:256]=As,[256:512]=Vs
__device__ __half g_loc[(size_t)MM * PP];     // local fp16 [M][256]
__device__ int    g_idx[MM * KNB];
__device__ float  g_tf[2 * PP];               // epilogue bias: t for cols<256, 0 else

__device__ __forceinline__ void split_hf(float v, __half& h, __half& l) {
    h = __float2half_rn(v);
    l = __float2half_rn(v - __half2float(h));
}

// ===================== fused prep: features split + weights =================
__global__ void prep_all_kernel(const float4* __restrict__ f,
                                const float* __restrict__ W_down,
                                const float* __restrict__ W_edge,
                                const float* __restrict__ W_up,
                                const float* __restrict__ b_edge,
                                const float* __restrict__ gamma,
                                const float* __restrict__ beta,
                                const float* __restrict__ mean,
                                const float* __restrict__ var) {
    int t = blockIdx.x * blockDim.x + threadIdx.x;
    if (t < MM * DD / 4) {               // features -> fp16
        float4 v = f[t];
        __half hh[4];
        hh[0] = __float2half_rn(v.x);
        hh[1] = __float2half_rn(v.y);
        hh[2] = __float2half_rn(v.z);
        hh[3] = __float2half_rn(v.w);
        *(uint2*)(g_fa + 4 * (size_t)t) = *(uint2*)hh;
    }
    if (t < PP * DD) {                   // W_down^T single fp16
        g_wdT[t] = __float2half_rn(W_down[(size_t)(t & 1023) * PP + (t >> 10)]);
    }
    if (t < DD * PP) {                   // W_up^T fp16 hi/lo
        float v = W_up[(size_t)(t & 255) * DD + (t >> 8)];
        split_hf(v, g_wuT_h[t], g_wuT_l[t]);
    }
    if (t < 2 * PP * PP) {               // s-scaled Wcomb^T hi/lo
        int p = t >> 8, ff = t & 255;
        int pc = p & 255;
        float sv = gamma[pc] * rsqrtf(var[pc] + 1e-5f);
        float v = (p < PP) ? (W_edge[ff * PP + p] - W_edge[(ff + PP) * PP + p])
                           : W_edge[(ff + PP) * PP + (p - PP)];
        split_hf(sv * v, g_wcT_h[t], g_wcT_l[t]);
    }
    if (t < 2 * PP) {
        if (t < PP) {
            float rs = rsqrtf(var[t] + 1e-5f);
            float sv = gamma[t] * rs;
            g_tf[t] = beta[t] - mean[t] * sv + sv * b_edge[t];
        } else {
            g_tf[t] = 0.0f;
        }
    }
}

// ===================== KNN: warp-per-point, 32-bit exact extraction =========
__global__ __launch_bounds__(256) void knn_kernel(const float* __restrict__ pts) {
    const int b    = blockIdx.y;
    const int warp = threadIdx.x >> 5;
    const int lane = threadIdx.x & 31;
    const int n    = blockIdx.x * 8 + warp;

    __shared__ float4 sp[NN];     // 16 KB: (x, y, z, |p|^2)
    for (int m = threadIdx.x; m < NN; m += 256) {
        float x = pts[((size_t)b * NN + m) * 3 + 0];
        float y = pts[((size_t)b * NN + m) * 3 + 1];
        float z = pts[((size_t)b * NN + m) * 3 + 2];
        sp[m] = make_float4(x, y, z, fmaf(x, x, fmaf(y, y, z * z)));
    }
    __syncthreads();

    const float4 P = sp[n];
    const float BIGF = 3.0e38f;

    float d[32];
    float pmin = BIGF;
#pragma unroll
    for (int j = 0; j < 32; ++j) {
        float4 q = sp[j * 32 + lane];
        float dot = fmaf(P.x, q.x, fmaf(P.y, q.y, P.z * q.z));
        d[j] = fmaf(-2.0f, dot, P.w + q.w);
        pmin = fminf(pmin, d[j]);
    }

    const int base = ((b << 10) + n) * KNB;

#pragma unroll
    for (int r = 0; r < KNB; ++r) {
        float g = pmin;
#pragma unroll
        for (int s = 16; s; s >>= 1)
            g = fminf(g, __shfl_xor_sync(0xffffffffu, g, s));

        int jm = 99;
#pragma unroll
        for (int j = 31; j >= 0; --j)
            jm = (d[j] == g) ? j : jm;

        int mc = (pmin == g) ? (jm * 32 + lane) : 0x7FFFFFFF;
#pragma unroll
        for (int s = 16; s; s >>= 1) {
            int o = __shfl_xor_sync(0xffffffffu, mc, s);
            mc = o < mc ? o : mc;
        }
        if (lane == 0) g_idx[base + r] = mc;
        if (r == KNB - 1) break;

        const int jkill = (lane == (mc & 31)) ? (mc >> 5) : 64;
        pmin = BIGF;
#pragma unroll
        for (int j = 0; j < 32; ++j) {
            d[j] = (j == jkill) ? BIGF : d[j];
            pmin = fminf(pmin, d[j]);
        }
    }
}

// ===================== edge gather + max (BN folded upstream) ===============
__global__ __launch_bounds__(128) void edge_max_kernel() {
    const int bn = blockIdx.x;
    const int t  = threadIdx.x;        // 0..127 -> cols 2t, 2t+1
    const int b  = bn >> 10;

    __shared__ int sidx[KNB];
    if (t < KNB) sidx[t] = g_idx[bn * KNB + t];
    __syncthreads();

    const __half2* AB2 = (const __half2*)g_AB;   // row stride 256 half2
    float2 a = __half22float2(AB2[(size_t)bn * 256 + t]);

    float acc0 = 0.0f, acc1 = 0.0f;   // relu(max) == max with 0 floor
#pragma unroll
    for (int k = 0; k < KNB; ++k) {
        float2 v = __half22float2(AB2[(size_t)((b << 10) + sidx[k]) * 256 + 128 + t]);
        acc0 = fmaxf(acc0, a.x + v.x);
        acc1 = fmaxf(acc1, a.y + v.y);
    }
    ((__half2*)g_loc)[(size_t)bn * 128 + t] = __floats2half2_rn(acc0, acc1);
}

// ===================== GEMM fp16, 1- or 2-term B, 2-stage, k-chunk 64 =======
// C = A(fp16) @ (Bh [+ Bl])^T ; B stored [N][K].
// EPI 1: relu(acc+bias)->fp16 ; EPI 2: acc+bias+res->f32 ; EPI 3: (acc+bias)->fp16.
template <int EPI, int TERMS>
__global__ void __launch_bounds__(256, 2) gemm_f16(
    const __half* __restrict__ A,
    const __half* __restrict__ Bh, const __half* __restrict__ Bl,
    int K, int Nc,
    __half* __restrict__ Ch, float* __restrict__ Cf,
    const float* __restrict__ bias, const float* __restrict__ res)
{
    extern __shared__ char smraw[];
    const uint32_t smb = smem_u32(smraw);   // 2 buffers x 48KB: [A | Bh | Bl]
    const int tid = threadIdx.x, lane = tid & 31, wid = tid >> 5;
    const int warp_m = wid & 3, warp_n = wid >> 2;
    const int bm = blockIdx.y, bn = blockIdx.x;

    const uint64_t gA  = cvta_g(A  + (size_t)(bm * 128) * K);
    const uint64_t gBh = cvta_g(Bh + (size_t)(bn * 128) * K);
    const uint64_t gBl = (TERMS == 2) ? cvta_g(Bl + (size_t)(bn * 128) * K) : 0;
    const int nk = K >> 6;

    const int grp = lane >> 3, rr = lane & 7;
    const int a_row0 = warp_m * 32 + ((grp & 1) << 3) + rr;
    const int kadd_a = (grp >> 1) << 4;
    const int b_row0 = warp_n * 64 + ((grp >> 1) << 3) + rr;
    const int kadd_b = (grp & 1) << 4;

    float acc[2][8][4];
#pragma unroll
    for (int i = 0; i < 2; ++i)
#pragma unroll
        for (int j = 0; j < 8; ++j)
#pragma unroll
            for (int c = 0; c < 4; ++c) acc[i][j][c] = 0.0f;

    auto issue = [&](int kc) {
        const uint32_t bb = (uint32_t)(kc & 1) * 49152u;
        const int kof = kc * 64;
#pragma unroll
        for (int i = 0; i < 4; ++i) {
            int idx = i * 256 + tid;
            int row = idx >> 3, g = idx & 7;
            int kel = kof + g * 8;
            uint32_t dst = SMEM_SWIZZLE_128B((uint32_t)(row * 128 + g * 16));
            size_t src = (size_t)row * K + kel;
            CP_ASYNC16(smb + bb + dst,         gA  + src * 2);
            CP_ASYNC16(smb + bb + 16384 + dst, gBh + src * 2);
            if (TERMS == 2)
                CP_ASYNC16(smb + bb + 32768 + dst, gBl + src * 2);
        }
    };

    issue(0); CP_COMMIT();

    for (int kc = 0; kc < nk; ++kc) {
        if (kc + 1 < nk) issue(kc + 1);
        CP_COMMIT();
        CP_WAIT(1);
        __syncthreads();

        const uint32_t bufA  = smb + (uint32_t)(kc & 1) * 49152u;
        const uint32_t bufBh = bufA + 16384;
        const uint32_t bufBl = bufA + 32768;

#pragma unroll
        for (int s = 0; s < 4; ++s) {
            uint32_t af[2][4];
#pragma unroll
            for (int mt = 0; mt < 2; ++mt) {
                int row = a_row0 + mt * 16;
                uint32_t rb = bufA + row * 128;
                uint32_t xr = (row & 7) << 4;
                LDSM_X4(af[mt][0], af[mt][1], af[mt][2], af[mt][3],
                        rb + (((uint32_t)(s * 32 + kadd_a)) ^ xr));
            }
#pragma unroll
            for (int jg = 0; jg < 2; ++jg) {
                uint32_t bh[4][2], bl[4][2];
#pragma unroll
                for (int p = 0; p < 2; ++p) {
                    int row = b_row0 + jg * 32 + p * 16;
                    uint32_t xr = (row & 7) << 4;
                    uint32_t by = (uint32_t)(s * 32 + kadd_b);
                    LDSM_X4(bh[2 * p][0], bh[2 * p][1], bh[2 * p + 1][0], bh[2 * p + 1][1],
                            bufBh + row * 128 + (by ^ xr));
                    if (TERMS == 2)
                        LDSM_X4(bl[2 * p][0], bl[2 * p][1], bl[2 * p + 1][0], bl[2 * p + 1][1],
                                bufBl + row * 128 + (by ^ xr));
                }
#pragma unroll
                for (int mt = 0; mt < 2; ++mt)
#pragma unroll
                    for (int j = 0; j < 4; ++j) {
                        float* d = acc[mt][jg * 4 + j];
                        MMA_F16(d, af[mt], bh[j]);
                        if (TERMS == 2)
                            MMA_F16(d, af[mt], bl[j]);
                    }
            }
        }
        __syncthreads();
    }

#pragma unroll
    for (int mt = 0; mt < 2; ++mt)
#pragma unroll
        for (int half = 0; half < 2; ++half) {
            size_t row = (size_t)bm * 128 + warp_m * 32 + mt * 16 + half * 8 + (lane >> 2);
#pragma unroll
            for (int j = 0; j < 8; ++j) {
                int col = bn * 128 + warp_n * 64 + j * 8 + 2 * (lane & 3);
                float v0 = acc[mt][j][half * 2 + 0];
                float v1 = acc[mt][j][half * 2 + 1];
                if (EPI == 1) {
                    v0 = fmaxf(v0 + bias[col], 0.0f);
                    v1 = fmaxf(v1 + bias[col + 1], 0.0f);
                    __half2 hv; hv.x = __float2half_rn(v0); hv.y = __float2half_rn(v1);
                    *(__half2*)(Ch + row * Nc + col) = hv;
                } else if (EPI == 3) {
                    v0 = v0 + bias[col];
                    v1 = v1 + bias[col + 1];
                    __half2 hv; hv.x = __float2half_rn(v0); hv.y = __float2half_rn(v1);
                    *(__half2*)(Ch + row * Nc + col) = hv;
                } else {
                    float2 r = *(const float2*)(res + row * Nc + col);
                    *(float2*)(Cf + row * Nc + col) =
                        make_float2(v0 + bias[col] + r.x, v1 + bias[col + 1] + r.y);
                }
            }
        }
}

// ===================== launch ===============================================
extern "C" void kernel_launch(void* const* d_in, const int* in_sizes, int n_in,
                              void* d_out, int out_size)
{
    const float* points   = (const float*)d_in[0];
    const float* features = (const float*)d_in[1];
    const float* W_down   = (const float*)d_in[2];
    const float* b_down   = (const float*)d_in[3];
    const float* W_edge   = (const float*)d_in[4];
    const float* b_edge   = (const float*)d_in[5];
    const float* gamma    = (const float*)d_in[6];
    const float* beta     = (const float*)d_in[7];
    const float* mean     = (const float*)d_in[8];
    const float* var      = (const float*)d_in[9];
    const float* W_up     = (const float*)d_in[10];
    const float* b_up     = (const float*)d_in[11];
    float* out = (float*)d_out;

    const int SMEM_DYN = 98304;
    static bool init_done = false;
    static cudaStream_t s2 = nullptr;
    static cudaEvent_t ev_fork = nullptr, ev_join = nullptr;
    if (!init_done) {
        cudaFuncSetAttribute((const void*)gemm_f16<1, 1>, cudaFuncAttributeMaxDynamicSharedMemorySize, SMEM_DYN);
        cudaFuncSetAttribute((const void*)gemm_f16<3, 2>, cudaFuncAttributeMaxDynamicSharedMemorySize, SMEM_DYN);
        cudaFuncSetAttribute((const void*)gemm_f16<2, 2>, cudaFuncAttributeMaxDynamicSharedMemorySize, SMEM_DYN);
        cudaStreamCreateWithFlags(&s2, cudaStreamNonBlocking);
        cudaEventCreateWithFlags(&ev_fork, cudaEventDisableTiming);
        cudaEventCreateWithFlags(&ev_join, cudaEventDisableTiming);
        init_done = true;
    }

    void *p_fa, *p_wd, *p_wch, *p_wcl, *p_wuh, *p_wul;
    void *p_fl, *p_ab, *p_loc, *p_tf;
    cudaGetSymbolAddress(&p_fa,  g_fa);
    cudaGetSymbolAddress(&p_wd,  g_wdT);
    cudaGetSymbolAddress(&p_wch, g_wcT_h); cudaGetSymbolAddress(&p_wcl, g_wcT_l);
    cudaGetSymbolAddress(&p_wuh, g_wuT_h); cudaGetSymbolAddress(&p_wul, g_wuT_l);
    cudaGetSymbolAddress(&p_fl,  g_fl);
    cudaGetSymbolAddress(&p_ab,  g_AB);
    cudaGetSymbolAddress(&p_loc, g_loc);
    cudaGetSymbolAddress(&p_tf,  g_tf);

    // ---- fork: KNN runs on s2, concurrent with the feature/GEMM chain ----
    cudaEventRecord(ev_fork, 0);
    cudaStreamWaitEvent(s2, ev_fork, 0);
    knn_kernel<<<dim3(NN / 8, BB), 256, 0, s2>>>(points);
    cudaEventRecord(ev_join, s2);

    // ---- main stream: fused prep + GEMM1 + GEMM2 ----
    prep_all_kernel<<<(MM * DD / 4 + 255) / 256, 256>>>(
        (const float4*)features, W_down, W_edge, W_up,
        b_edge, gamma, beta, mean, var);

    // feats_low = relu(features @ W_down + b_down)  [M=16384, N=256, K=1024], 1-term
    gemm_f16<1, 1><<<dim3(PP / 128, MM / 128), 256, SMEM_DYN>>>(
        (const __half*)p_fa, (const __half*)p_wd, nullptr,
        DD, PP, (__half*)p_fl, nullptr, b_down, nullptr);

    // AB = feats_low @ (s-scaled Wcomb) + tf        [M, N=512, K=256], 2-term
    gemm_f16<3, 2><<<dim3(2 * PP / 128, MM / 128), 256, SMEM_DYN>>>(
        (const __half*)p_fl, (const __half*)p_wch, (const __half*)p_wcl,
        PP, 2 * PP, (__half*)p_ab, nullptr, (const float*)p_tf, nullptr);

    // ---- join: edge_max needs both KNN (s2) and GEMM2 (main) ----
    cudaStreamWaitEvent(0, ev_join, 0);
    edge_max_kernel<<<MM, 128>>>();

    // out = features + local @ W_up + b_up          [M, N=1024, K=256], 2-term
    gemm_f16<2, 2><<<dim3(DD / 128, MM / 128), 256, SMEM_DYN>>>(
        (const __half*)p_loc, (const __half*)p_wuh, (const __half*)p_wul,
        PP, DD, nullptr, out, b_up, features);
}

// round 12
// speedup vs baseline: 1.6107x; 1.0708x over previous
#include <cuda_runtime.h>
#include <cuda_bf16.h>
#include <cuda_fp16.h>
#include <cstdint>
#include <cfloat>

#define BB   16
#define NN   1024
#define DD   1024
#define PP   256
#define KNB  16
#define MM   (BB * NN)     // 16384

// ===================== helpers ==============================================
__device__ __forceinline__ uint32_t smem_u32(const void* p) {
    uint32_t a;
    asm("{ .reg .u64 t; cvta.to.shared.u64 t, %1; cvt.u32.u64 %0, t; }" : "=r"(a) : "l"(p));
    return a;
}
__device__ __forceinline__ uint64_t cvta_g(const void* p) {
    uint64_t r; asm("cvta.to.global.u64 %0, %1;" : "=l"(r) : "l"(p)); return r;
}
#define SMEM_SWIZZLE_128B(off) ((off) ^ (((off) >> 3) & 0x70))

#define CP_ASYNC16(dst, src) \
    asm volatile("cp.async.cg.shared.global [%0], [%1], 16;" :: "r"(dst), "l"(src) : "memory")
#define CP_COMMIT() asm volatile("cp.async.commit_group;" ::: "memory")
#define CP_WAIT(n)  asm volatile("cp.async.wait_group %0;" :: "n"(n) : "memory")

#define LDSM_X4(r0, r1, r2, r3, addr) \
    asm volatile("ldmatrix.sync.aligned.m8n8.x4.shared.b16 {%0,%1,%2,%3}, [%4];" \
                 : "=r"(r0), "=r"(r1), "=r"(r2), "=r"(r3) : "r"(addr))

#define MMA_F16(d, a, b) \
    asm volatile("mma.sync.aligned.m16n8k16.row.col.f32.f16.f16.f32 " \
                 "{%0,%1,%2,%3}, {%4,%5,%6,%7}, {%8,%9}, {%0,%1,%2,%3};" \
                 : "+f"((d)[0]), "+f"((d)[1]), "+f"((d)[2]), "+f"((d)[3]) \
                 : "r"((a)[0]), "r"((a)[1]), "r"((a)[2]), "r"((a)[3]), \
                   "r"((b)[0]), "r"((b)[1]))

// ===================== scratch ==============================================
__device__ __half g_fa[(size_t)MM * DD];      // features fp16 [M][1024]
__device__ __half g_wdT[PP * DD];             // W_down^T fp16 [256][1024]
__device__ __half g_wcT[2 * PP * PP];         // s-scaled Wcomb^T fp16 [512][256]
__device__ __half g_wuT[DD * PP];             // W_up^T fp16 [1024][256]
__device__ __half g_fl[(size_t)MM * PP];      // feats_low fp16 [M][256]
__device__ __half g_AB[(size_t)MM * 2 * PP];  // fp16 [M][0:256]=As,[256:512]=Vs
__device__ __half g_loc[(size_t)MM * PP];     // local fp16 [M][256]
__device__ int    g_idx[MM * KNB];
__device__ float  g_tf[2 * PP];               // epilogue bias: t for cols<256, 0 else

// ===================== fused prep: features split + weights =================
__global__ void prep_all_kernel(const float4* __restrict__ f,
                                const float* __restrict__ W_down,
                                const float* __restrict__ W_edge,
                                const float* __restrict__ W_up,
                                const float* __restrict__ b_edge,
                                const float* __restrict__ gamma,
                                const float* __restrict__ beta,
                                const float* __restrict__ mean,
                                const float* __restrict__ var) {
    int t = blockIdx.x * blockDim.x + threadIdx.x;
    if (t < MM * DD / 4) {               // features -> fp16
        float4 v = f[t];
        __half hh[4];
        hh[0] = __float2half_rn(v.x);
        hh[1] = __float2half_rn(v.y);
        hh[2] = __float2half_rn(v.z);
        hh[3] = __float2half_rn(v.w);
        *(uint2*)(g_fa + 4 * (size_t)t) = *(uint2*)hh;
    }
    if (t < PP * DD) {                   // W_down^T fp16
        g_wdT[t] = __float2half_rn(W_down[(size_t)(t & 1023) * PP + (t >> 10)]);
    }
    if (t < DD * PP) {                   // W_up^T fp16
        g_wuT[t] = __float2half_rn(W_up[(size_t)(t & 255) * DD + (t >> 8)]);
    }
    if (t < 2 * PP * PP) {               // s-scaled Wcomb^T fp16
        int p = t >> 8, ff = t & 255;
        int pc = p & 255;
        float sv = gamma[pc] * rsqrtf(var[pc] + 1e-5f);
        float v = (p < PP) ? (W_edge[ff * PP + p] - W_edge[(ff + PP) * PP + p])
                           : W_edge[(ff + PP) * PP + (p - PP)];
        g_wcT[t] = __float2half_rn(sv * v);
    }
    if (t < 2 * PP) {
        if (t < PP) {
            float rs = rsqrtf(var[t] + 1e-5f);
            float sv = gamma[t] * rs;
            g_tf[t] = beta[t] - mean[t] * sv + sv * b_edge[t];
        } else {
            g_tf[t] = 0.0f;
        }
    }
}

// ===================== KNN: warp-per-point, exact extraction, tree rescan ===
__global__ __launch_bounds__(256) void knn_kernel(const float* __restrict__ pts) {
    const int b    = blockIdx.y;
    const int warp = threadIdx.x >> 5;
    const int lane = threadIdx.x & 31;
    const int n    = blockIdx.x * 8 + warp;

    __shared__ float4 sp[NN];     // 16 KB: (x, y, z, |p|^2)
    for (int m = threadIdx.x; m < NN; m += 256) {
        float x = pts[((size_t)b * NN + m) * 3 + 0];
        float y = pts[((size_t)b * NN + m) * 3 + 1];
        float z = pts[((size_t)b * NN + m) * 3 + 2];
        sp[m] = make_float4(x, y, z, fmaf(x, x, fmaf(y, y, z * z)));
    }
    __syncthreads();

    const float4 P = sp[n];
    const float BIGF = 3.0e38f;

    float d[32];
#pragma unroll
    for (int j = 0; j < 32; ++j) {
        float4 q = sp[j * 32 + lane];
        float dot = fmaf(P.x, q.x, fmaf(P.y, q.y, P.z * q.z));
        d[j] = fmaf(-2.0f, dot, P.w + q.w);
    }

    // exact tree min over local 32 (min is exact under reassociation)
    auto tree_min = [&](void) -> float {
        float t16[16];
#pragma unroll
        for (int j = 0; j < 16; ++j) t16[j] = fminf(d[2 * j], d[2 * j + 1]);
#pragma unroll
        for (int s = 8; s >= 1; s >>= 1)
#pragma unroll
            for (int j = 0; j < 8; ++j)
                if (j < s) t16[j] = fminf(t16[j], t16[j + s]);
        return t16[0];
    };

    float pmin = tree_min();
    const int base = ((b << 10) + n) * KNB;

#pragma unroll
    for (int r = 0; r < KNB; ++r) {
        float g = pmin;
#pragma unroll
        for (int s = 16; s; s >>= 1)
            g = fminf(g, __shfl_xor_sync(0xffffffffu, g, s));

        int jm = 99;
#pragma unroll
        for (int j = 31; j >= 0; --j)
            jm = (d[j] == g) ? j : jm;

        int mc = (pmin == g) ? (jm * 32 + lane) : 0x7FFFFFFF;
#pragma unroll
        for (int s = 16; s; s >>= 1) {
            int o = __shfl_xor_sync(0xffffffffu, mc, s);
            mc = o < mc ? o : mc;
        }
        if (lane == 0) g_idx[base + r] = mc;
        if (r == KNB - 1) break;

        const int jkill = (lane == (mc & 31)) ? (mc >> 5) : 64;
#pragma unroll
        for (int j = 0; j < 32; ++j)
            d[j] = (j == jkill) ? BIGF : d[j];
        pmin = tree_min();
    }
}

// ===================== edge gather + max (BN folded upstream) ===============
__global__ __launch_bounds__(128) void edge_max_kernel() {
    const int bn = blockIdx.x;
    const int t  = threadIdx.x;        // 0..127 -> cols 2t, 2t+1
    const int b  = bn >> 10;

    __shared__ int sidx[KNB];
    if (t < KNB) sidx[t] = g_idx[bn * KNB + t];
    __syncthreads();

    const __half2* AB2 = (const __half2*)g_AB;   // row stride 256 half2
    float2 a = __half22float2(AB2[(size_t)bn * 256 + t]);

    float acc0 = 0.0f, acc1 = 0.0f;   // relu(max) == max with 0 floor
#pragma unroll
    for (int k = 0; k < KNB; ++k) {
        float2 v = __half22float2(AB2[(size_t)((b << 10) + sidx[k]) * 256 + 128 + t]);
        acc0 = fmaxf(acc0, a.x + v.x);
        acc1 = fmaxf(acc1, a.y + v.y);
    }
    ((__half2*)g_loc)[(size_t)bn * 128 + t] = __floats2half2_rn(acc0, acc1);
}

// ===================== GEMM fp16 1-term, 2-stage, k-chunk 64 ================
// C = A(fp16) @ B(fp16)^T ; B stored [N][K].
// EPI 1: relu(acc+bias)->fp16 ; EPI 2: acc+bias+res->f32 ; EPI 3: (acc+bias)->fp16.
template <int EPI>
__global__ void __launch_bounds__(256, 2) gemm_f16(
    const __half* __restrict__ A, const __half* __restrict__ B,
    int K, int Nc,
    __half* __restrict__ Ch, float* __restrict__ Cf,
    const float* __restrict__ bias, const float* __restrict__ res)
{
    extern __shared__ char smraw[];
    const uint32_t smb = smem_u32(smraw);   // 2 buffers x 32KB: [A 16KB | B 16KB]
    const int tid = threadIdx.x, lane = tid & 31, wid = tid >> 5;
    const int warp_m = wid & 3, warp_n = wid >> 2;
    const int bm = blockIdx.y, bn = blockIdx.x;

    const uint64_t gA = cvta_g(A + (size_t)(bm * 128) * K);
    const uint64_t gB = cvta_g(B + (size_t)(bn * 128) * K);
    const int nk = K >> 6;

    const int grp = lane >> 3, rr = lane & 7;
    const int a_row0 = warp_m * 32 + ((grp & 1) << 3) + rr;
    const int kadd_a = (grp >> 1) << 4;
    const int b_row0 = warp_n * 64 + ((grp >> 1) << 3) + rr;
    const int kadd_b = (grp & 1) << 4;

    float acc[2][8][4];
#pragma unroll
    for (int i = 0; i < 2; ++i)
#pragma unroll
        for (int j = 0; j < 8; ++j)
#pragma unroll
            for (int c = 0; c < 4; ++c) acc[i][j][c] = 0.0f;

    auto issue = [&](int kc) {
        const uint32_t bb = (uint32_t)(kc & 1) * 32768u;
        const int kof = kc * 64;
#pragma unroll
        for (int i = 0; i < 4; ++i) {
            int idx = i * 256 + tid;
            int row = idx >> 3, g = idx & 7;
            int kel = kof + g * 8;
            uint32_t dst = SMEM_SWIZZLE_128B((uint32_t)(row * 128 + g * 16));
            size_t src = (size_t)row * K + kel;
            CP_ASYNC16(smb + bb + dst,         gA + src * 2);
            CP_ASYNC16(smb + bb + 16384 + dst, gB + src * 2);
        }
    };

    issue(0); CP_COMMIT();

    for (int kc = 0; kc < nk; ++kc) {
        if (kc + 1 < nk) issue(kc + 1);
        CP_COMMIT();
        CP_WAIT(1);
        __syncthreads();

        const uint32_t bufA = smb + (uint32_t)(kc & 1) * 32768u;
        const uint32_t bufB = bufA + 16384;

#pragma unroll
        for (int s = 0; s < 4; ++s) {
            uint32_t af[2][4];
#pragma unroll
            for (int mt = 0; mt < 2; ++mt) {
                int row = a_row0 + mt * 16;
                uint32_t rb = bufA + row * 128;
                uint32_t xr = (row & 7) << 4;
                LDSM_X4(af[mt][0], af[mt][1], af[mt][2], af[mt][3],
                        rb + (((uint32_t)(s * 32 + kadd_a)) ^ xr));
            }
#pragma unroll
            for (int jg = 0; jg < 2; ++jg) {
                uint32_t bf[4][2];
#pragma unroll
                for (int p = 0; p < 2; ++p) {
                    int row = b_row0 + jg * 32 + p * 16;
                    uint32_t xr = (row & 7) << 4;
                    uint32_t by = (uint32_t)(s * 32 + kadd_b);
                    LDSM_X4(bf[2 * p][0], bf[2 * p][1], bf[2 * p + 1][0], bf[2 * p + 1][1],
                            bufB + row * 128 + (by ^ xr));
                }
#pragma unroll
                for (int mt = 0; mt < 2; ++mt)
#pragma unroll
                    for (int j = 0; j < 4; ++j)
                        MMA_F16(acc[mt][jg * 4 + j], af[mt], bf[j]);
            }
        }
        __syncthreads();
    }

#pragma unroll
    for (int mt = 0; mt < 2; ++mt)
#pragma unroll
        for (int half = 0; half < 2; ++half) {
            size_t row = (size_t)bm * 128 + warp_m * 32 + mt * 16 + half * 8 + (lane >> 2);
#pragma unroll
            for (int j = 0; j < 8; ++j) {
                int col = bn * 128 + warp_n * 64 + j * 8 + 2 * (lane & 3);
                float v0 = acc[mt][j][half * 2 + 0];
                float v1 = acc[mt][j][half * 2 + 1];
                if (EPI == 1) {
                    v0 = fmaxf(v0 + bias[col], 0.0f);
                    v1 = fmaxf(v1 + bias[col + 1], 0.0f);
                    __half2 hv; hv.x = __float2half_rn(v0); hv.y = __float2half_rn(v1);
                    *(__half2*)(Ch + row * Nc + col) = hv;
                } else if (EPI == 3) {
                    v0 = v0 + bias[col];
                    v1 = v1 + bias[col + 1];
                    __half2 hv; hv.x = __float2half_rn(v0); hv.y = __float2half_rn(v1);
                    *(__half2*)(Ch + row * Nc + col) = hv;
                } else {
                    float2 r = *(const float2*)(res + row * Nc + col);
                    *(float2*)(Cf + row * Nc + col) =
                        make_float2(v0 + bias[col] + r.x, v1 + bias[col + 1] + r.y);
                }
            }
        }
}

// ===================== launch ===============================================
extern "C" void kernel_launch(void* const* d_in, const int* in_sizes, int n_in,
                              void* d_out, int out_size)
{
    const float* points   = (const float*)d_in[0];
    const float* features = (const float*)d_in[1];
    const float* W_down   = (const float*)d_in[2];
    const float* b_down   = (const float*)d_in[3];
    const float* W_edge   = (const float*)d_in[4];
    const float* b_edge   = (const float*)d_in[5];
    const float* gamma    = (const float*)d_in[6];
    const float* beta     = (const float*)d_in[7];
    const float* mean     = (const float*)d_in[8];
    const float* var      = (const float*)d_in[9];
    const float* W_up     = (const float*)d_in[10];
    const float* b_up     = (const float*)d_in[11];
    float* out = (float*)d_out;

    const int SMEM_DYN = 65536;
    static bool init_done = false;
    static cudaStream_t s2 = nullptr;
    static cudaEvent_t ev_fork = nullptr, ev_join = nullptr;
    if (!init_done) {
        cudaFuncSetAttribute((const void*)gemm_f16<1>, cudaFuncAttributeMaxDynamicSharedMemorySize, SMEM_DYN);
        cudaFuncSetAttribute((const void*)gemm_f16<2>, cudaFuncAttributeMaxDynamicSharedMemorySize, SMEM_DYN);
        cudaFuncSetAttribute((const void*)gemm_f16<3>, cudaFuncAttributeMaxDynamicSharedMemorySize, SMEM_DYN);
        cudaStreamCreateWithFlags(&s2, cudaStreamNonBlocking);
        cudaEventCreateWithFlags(&ev_fork, cudaEventDisableTiming);
        cudaEventCreateWithFlags(&ev_join, cudaEventDisableTiming);
        init_done = true;
    }

    void *p_fa, *p_wd, *p_wc, *p_wu, *p_fl, *p_ab, *p_loc, *p_tf;
    cudaGetSymbolAddress(&p_fa,  g_fa);
    cudaGetSymbolAddress(&p_wd,  g_wdT);
    cudaGetSymbolAddress(&p_wc,  g_wcT);
    cudaGetSymbolAddress(&p_wu,  g_wuT);
    cudaGetSymbolAddress(&p_fl,  g_fl);
    cudaGetSymbolAddress(&p_ab,  g_AB);
    cudaGetSymbolAddress(&p_loc, g_loc);
    cudaGetSymbolAddress(&p_tf,  g_tf);

    // ---- fork: KNN runs on s2, concurrent with the feature/GEMM chain ----
    cudaEventRecord(ev_fork, 0);
    cudaStreamWaitEvent(s2, ev_fork, 0);
    knn_kernel<<<dim3(NN / 8, BB), 256, 0, s2>>>(points);
    cudaEventRecord(ev_join, s2);

    // ---- main stream: fused prep + GEMM1 + GEMM2 ----
    prep_all_kernel<<<(MM * DD / 4 + 255) / 256, 256>>>(
        (const float4*)features, W_down, W_edge, W_up,
        b_edge, gamma, beta, mean, var);

    // feats_low = relu(features @ W_down + b_down)  [M=16384, N=256, K=1024]
    gemm_f16<1><<<dim3(PP / 128, MM / 128), 256, SMEM_DYN>>>(
        (const __half*)p_fa, (const __half*)p_wd,
        DD, PP, (__half*)p_fl, nullptr, b_down, nullptr);

    // AB = feats_low @ (s-scaled Wcomb) + tf        [M, N=512, K=256]
    gemm_f16<3><<<dim3(2 * PP / 128, MM / 128), 256, SMEM_DYN>>>(
        (const __half*)p_fl, (const __half*)p_wc,
        PP, 2 * PP, (__half*)p_ab, nullptr, (const float*)p_tf, nullptr);

    // ---- join: edge_max needs both KNN (s2) and GEMM2 (main) ----
    cudaStreamWaitEvent(0, ev_join, 0);
    edge_max_kernel<<<MM, 128>>>();

    // out = features + local @ W_up + b_up          [M, N=1024, K=256]
    gemm_f16<2><<<dim3(DD / 128, MM / 128), 256, SMEM_DYN>>>(
        (const __half*)p_loc, (const __half*)p_wu,
        PP, DD, nullptr, out, b_up, features);
}

// round 13
// speedup vs baseline: 2.1823x; 1.3549x over previous
#include <cuda_runtime.h>
#include <cuda_bf16.h>
#include <cuda_fp16.h>
#include <cstdint>
#include <cfloat>

#define BB   16
#define NN   1024
#define DD   1024
#define PP   256
#define KNB  16
#define MM   (BB * NN)     // 16384

// ===================== helpers ==============================================
__device__ __forceinline__ uint32_t smem_u32(const void* p) {
    uint32_t a;
    asm("{ .reg .u64 t; cvta.to.shared.u64 t, %1; cvt.u32.u64 %0, t; }" : "=r"(a) : "l"(p));
    return a;
}
__device__ __forceinline__ uint64_t cvta_g(const void* p) {
    uint64_t r; asm("cvta.to.global.u64 %0, %1;" : "=l"(r) : "l"(p)); return r;
}
#define SMEM_SWIZZLE_128B(off) ((off) ^ (((off) >> 3) & 0x70))

#define CP_ASYNC16(dst, src) \
    asm volatile("cp.async.cg.shared.global [%0], [%1], 16;" :: "r"(dst), "l"(src) : "memory")
#define CP_COMMIT() asm volatile("cp.async.commit_group;" ::: "memory")
#define CP_WAIT(n)  asm volatile("cp.async.wait_group %0;" :: "n"(n) : "memory")

#define LDSM_X4(r0, r1, r2, r3, addr) \
    asm volatile("ldmatrix.sync.aligned.m8n8.x4.shared.b16 {%0,%1,%2,%3}, [%4];" \
                 : "=r"(r0), "=r"(r1), "=r"(r2), "=r"(r3) : "r"(addr))

#define MMA_F16(d, a, b) \
    asm volatile("mma.sync.aligned.m16n8k16.row.col.f32.f16.f16.f32 " \
                 "{%0,%1,%2,%3}, {%4,%5,%6,%7}, {%8,%9}, {%0,%1,%2,%3};" \
                 : "+f"((d)[0]), "+f"((d)[1]), "+f"((d)[2]), "+f"((d)[3]) \
                 : "r"((a)[0]), "r"((a)[1]), "r"((a)[2]), "r"((a)[3]), \
                   "r"((b)[0]), "r"((b)[1]))

// ===================== scratch ==============================================
__device__ __half g_fa[(size_t)MM * DD];      // features fp16 [M][1024]
__device__ __half g_wdT[PP * DD];             // W_down^T fp16 [256][1024]
__device__ __half g_wcT[2 * PP * PP];         // s-scaled Wcomb^T fp16 [512][256]
__device__ __half g_wuT[DD * PP];             // W_up^T fp16 [1024][256]
__device__ __half g_fl[(size_t)MM * PP];      // feats_low fp16 [M][256]
__device__ __half g_AB[(size_t)MM * 2 * PP];  // fp16 [M][0:256]=As,[256:512]=Vs
__device__ __half g_loc[(size_t)MM * PP];     // local fp16 [M][256]
__device__ int    g_idx[MM * KNB];
__device__ float  g_tf[2 * PP];               // epilogue bias: t for cols<256, 0 else

// ===================== fused prep ===========================================
__global__ void prep_all_kernel(const float4* __restrict__ f,
                                const float* __restrict__ W_down,
                                const float* __restrict__ W_edge,
                                const float* __restrict__ W_up,
                                const float* __restrict__ b_edge,
                                const float* __restrict__ gamma,
                                const float* __restrict__ beta,
                                const float* __restrict__ mean,
                                const float* __restrict__ var) {
    int t = blockIdx.x * blockDim.x + threadIdx.x;
    if (t < MM * DD / 4) {
        float4 v = f[t];
        __half hh[4];
        hh[0] = __float2half_rn(v.x);
        hh[1] = __float2half_rn(v.y);
        hh[2] = __float2half_rn(v.z);
        hh[3] = __float2half_rn(v.w);
        *(uint2*)(g_fa + 4 * (size_t)t) = *(uint2*)hh;
    }
    if (t < PP * DD)
        g_wdT[t] = __float2half_rn(W_down[(size_t)(t & 1023) * PP + (t >> 10)]);
    if (t < DD * PP)
        g_wuT[t] = __float2half_rn(W_up[(size_t)(t & 255) * DD + (t >> 8)]);
    if (t < 2 * PP * PP) {
        int p = t >> 8, ff = t & 255;
        int pc = p & 255;
        float sv = gamma[pc] * rsqrtf(var[pc] + 1e-5f);
        float v = (p < PP) ? (W_edge[ff * PP + p] - W_edge[(ff + PP) * PP + p])
                           : W_edge[(ff + PP) * PP + (p - PP)];
        g_wcT[t] = __float2half_rn(sv * v);
    }
    if (t < 2 * PP) {
        if (t < PP) {
            float rs = rsqrtf(var[t] + 1e-5f);
            float sv = gamma[t] * rs;
            g_tf[t] = beta[t] - mean[t] * sv + sv * b_edge[t];
        } else {
            g_tf[t] = 0.0f;
        }
    }
}

// ===================== KNN: threshold + bitonic (exact set) =================
__device__ __forceinline__ bool key_less(float v1, int m1, float v2, int m2) {
    return (v1 < v2) || (v1 == v2 && m1 < m2);
}
// bitonic sort across warp lanes, ascending by key (v,m). Keys distinct.
__device__ __forceinline__ void sort32(float& v, int& m, int lane) {
#pragma unroll
    for (int k = 2; k <= 32; k <<= 1) {
#pragma unroll
        for (int j = 16; j > 0; j >>= 1) {
            if (j >= k) continue;
            float v2 = __shfl_xor_sync(0xffffffffu, v, j);
            int   m2 = __shfl_xor_sync(0xffffffffu, m, j);
            bool take_min = ((lane & k) == 0) == ((lane & j) == 0);
            bool pl = key_less(v2, m2, v, m);     // partner < mine
            bool take_partner = (pl == take_min);
            v = take_partner ? v2 : v;
            m = take_partner ? m2 : m;
        }
    }
}

__global__ __launch_bounds__(256) void knn_kernel(const float* __restrict__ pts) {
    const int b    = blockIdx.y;
    const int warp = threadIdx.x >> 5;
    const int lane = threadIdx.x & 31;
    const int n    = blockIdx.x * 8 + warp;

    __shared__ float4 sp[NN];          // 16 KB
    __shared__ float  s_cd[8][32];
    __shared__ int    s_cm[8][32];

    for (int m = threadIdx.x; m < NN; m += 256) {
        float x = pts[((size_t)b * NN + m) * 3 + 0];
        float y = pts[((size_t)b * NN + m) * 3 + 1];
        float z = pts[((size_t)b * NN + m) * 3 + 2];
        sp[m] = make_float4(x, y, z, fmaf(x, x, fmaf(y, y, z * z)));
    }
    __syncthreads();

    const float4 P = sp[n];
    const float BIGF = 3.0e38f;

    float d[32];
#pragma unroll
    for (int j = 0; j < 32; ++j) {
        float4 q = sp[j * 32 + lane];
        float dot = fmaf(P.x, q.x, fmaf(P.y, q.y, P.z * q.z));
        d[j] = fmaf(-2.0f, dot, P.w + q.w);
    }

    // per-lane min with index
    float pv = d[0];
    int   pj = 0;
#pragma unroll
    for (int j = 1; j < 32; ++j) {
        bool c = d[j] < pv;            // in-lane ties -> keep smaller j (= smaller m)
        pv = c ? d[j] : pv;
        pj = c ? j : pj;
    }
    int pm = pj * 32 + lane;

    // sort lane minima; tau = 16th smallest lane-min key
    float sv = pv; int sm = pm;
    sort32(sv, sm, lane);
    float tv = __shfl_sync(0xffffffffu, sv, 15);
    int   tm = __shfl_sync(0xffffffffu, sm, 15);

    // collect all keys <= tau (exact superset of global top-16)
    int cbase = 0;
#pragma unroll
    for (int j = 0; j < 32; ++j) {
        int m = j * 32 + lane;
        bool sel = key_less(d[j], m, tv, tm) || (d[j] == tv && m == tm);
        unsigned msk = __ballot_sync(0xffffffffu, sel);
        int pos = cbase + __popc(msk & ((1u << lane) - 1u));
        if (sel && pos < 32) { s_cd[warp][pos] = d[j]; s_cm[warp][pos] = m; }
        cbase += __popc(msk);
    }
    __syncwarp();

    const int base = ((b << 10) + n) * KNB;

    if (cbase <= 32) {
        float v = (lane < cbase) ? s_cd[warp][lane] : BIGF;
        int   m = (lane < cbase) ? s_cm[warp][lane] : 0x7FFFFFFF;
        sort32(v, m, lane);
        if (lane < KNB) g_idx[base + lane] = m;
    } else {
        // fallback: exact 16-round extraction (rare)
        auto tree_min = [&](void) -> float {
            float t16[16];
#pragma unroll
            for (int j = 0; j < 16; ++j) t16[j] = fminf(d[2 * j], d[2 * j + 1]);
#pragma unroll
            for (int s = 8; s >= 1; s >>= 1)
#pragma unroll
                for (int j = 0; j < 8; ++j)
                    if (j < s) t16[j] = fminf(t16[j], t16[j + s]);
            return t16[0];
        };
        float pmin = tree_min();
#pragma unroll
        for (int r = 0; r < KNB; ++r) {
            float g = pmin;
#pragma unroll
            for (int s = 16; s; s >>= 1)
                g = fminf(g, __shfl_xor_sync(0xffffffffu, g, s));
            int jm = 99;
#pragma unroll
            for (int j = 31; j >= 0; --j)
                jm = (d[j] == g) ? j : jm;
            int mc = (pmin == g) ? (jm * 32 + lane) : 0x7FFFFFFF;
#pragma unroll
            for (int s = 16; s; s >>= 1) {
                int o = __shfl_xor_sync(0xffffffffu, mc, s);
                mc = o < mc ? o : mc;
            }
            if (lane == 0) g_idx[base + r] = mc;
            if (r == KNB - 1) break;
            const int jkill = (lane == (mc & 31)) ? (mc >> 5) : 64;
#pragma unroll
            for (int j = 0; j < 32; ++j)
                d[j] = (j == jkill) ? BIGF : d[j];
            pmin = tree_min();
        }
    }
}

// ===================== edge gather + max (BN folded upstream) ===============
__global__ __launch_bounds__(128) void edge_max_kernel() {
    const int bn = blockIdx.x;
    const int t  = threadIdx.x;
    const int b  = bn >> 10;

    __shared__ int sidx[KNB];
    if (t < KNB) sidx[t] = g_idx[bn * KNB + t];
    __syncthreads();

    const __half2* AB2 = (const __half2*)g_AB;
    float2 a = __half22float2(AB2[(size_t)bn * 256 + t]);

    float acc0 = 0.0f, acc1 = 0.0f;
#pragma unroll
    for (int k = 0; k < KNB; ++k) {
        float2 v = __half22float2(AB2[(size_t)((b << 10) + sidx[k]) * 256 + 128 + t]);
        acc0 = fmaxf(acc0, a.x + v.x);
        acc1 = fmaxf(acc1, a.y + v.y);
    }
    ((__half2*)g_loc)[(size_t)bn * 128 + t] = __floats2half2_rn(acc0, acc1);
}

// ===================== GEMM fp16 1-term, 2-stage, k-chunk 64 ================
template <int EPI>
__global__ void __launch_bounds__(256, 2) gemm_f16(
    const __half* __restrict__ A, const __half* __restrict__ B,
    int K, int Nc,
    __half* __restrict__ Ch, float* __restrict__ Cf,
    const float* __restrict__ bias, const float* __restrict__ res)
{
    extern __shared__ char smraw[];
    const uint32_t smb = smem_u32(smraw);
    const int tid = threadIdx.x, lane = tid & 31, wid = tid >> 5;
    const int warp_m = wid & 3, warp_n = wid >> 2;
    const int bm = blockIdx.y, bn = blockIdx.x;

    const uint64_t gA = cvta_g(A + (size_t)(bm * 128) * K);
    const uint64_t gB = cvta_g(B + (size_t)(bn * 128) * K);
    const int nk = K >> 6;

    const int grp = lane >> 3, rr = lane & 7;
    const int a_row0 = warp_m * 32 + ((grp & 1) << 3) + rr;
    const int kadd_a = (grp >> 1) << 4;
    const int b_row0 = warp_n * 64 + ((grp >> 1) << 3) + rr;
    const int kadd_b = (grp & 1) << 4;

    float acc[2][8][4];
#pragma unroll
    for (int i = 0; i < 2; ++i)
#pragma unroll
        for (int j = 0; j < 8; ++j)
#pragma unroll
            for (int c = 0; c < 4; ++c) acc[i][j][c] = 0.0f;

    auto issue = [&](int kc) {
        const uint32_t bb = (uint32_t)(kc & 1) * 32768u;
        const int kof = kc * 64;
#pragma unroll
        for (int i = 0; i < 4; ++i) {
            int idx = i * 256 + tid;
            int row = idx >> 3, g = idx & 7;
            int kel = kof + g * 8;
            uint32_t dst = SMEM_SWIZZLE_128B((uint32_t)(row * 128 + g * 16));
            size_t src = (size_t)row * K + kel;
            CP_ASYNC16(smb + bb + dst,         gA + src * 2);
            CP_ASYNC16(smb + bb + 16384 + dst, gB + src * 2);
        }
    };

    issue(0); CP_COMMIT();

    for (int kc = 0; kc < nk; ++kc) {
        if (kc + 1 < nk) issue(kc + 1);
        CP_COMMIT();
        CP_WAIT(1);
        __syncthreads();

        const uint32_t bufA = smb + (uint32_t)(kc & 1) * 32768u;
        const uint32_t bufB = bufA + 16384;

#pragma unroll
        for (int s = 0; s < 4; ++s) {
            uint32_t af[2][4];
#pragma unroll
            for (int mt = 0; mt < 2; ++mt) {
                int row = a_row0 + mt * 16;
                uint32_t rb = bufA + row * 128;
                uint32_t xr = (row & 7) << 4;
                LDSM_X4(af[mt][0], af[mt][1], af[mt][2], af[mt][3],
                        rb + (((uint32_t)(s * 32 + kadd_a)) ^ xr));
            }
#pragma unroll
            for (int jg = 0; jg < 2; ++jg) {
                uint32_t bf[4][2];
#pragma unroll
                for (int p = 0; p < 2; ++p) {
                    int row = b_row0 + jg * 32 + p * 16;
                    uint32_t xr = (row & 7) << 4;
                    uint32_t by = (uint32_t)(s * 32 + kadd_b);
                    LDSM_X4(bf[2 * p][0], bf[2 * p][1], bf[2 * p + 1][0], bf[2 * p + 1][1],
                            bufB + row * 128 + (by ^ xr));
                }
#pragma unroll
                for (int mt = 0; mt < 2; ++mt)
#pragma unroll
                    for (int j = 0; j < 4; ++j)
                        MMA_F16(acc[mt][jg * 4 + j], af[mt], bf[j]);
            }
        }
        __syncthreads();
    }

#pragma unroll
    for (int mt = 0; mt < 2; ++mt)
#pragma unroll
        for (int half = 0; half < 2; ++half) {
            size_t row = (size_t)bm * 128 + warp_m * 32 + mt * 16 + half * 8 + (lane >> 2);
#pragma unroll
            for (int j = 0; j < 8; ++j) {
                int col = bn * 128 + warp_n * 64 + j * 8 + 2 * (lane & 3);
                float v0 = acc[mt][j][half * 2 + 0];
                float v1 = acc[mt][j][half * 2 + 1];
                if (EPI == 1) {
                    v0 = fmaxf(v0 + bias[col], 0.0f);
                    v1 = fmaxf(v1 + bias[col + 1], 0.0f);
                    __half2 hv; hv.x = __float2half_rn(v0); hv.y = __float2half_rn(v1);
                    *(__half2*)(Ch + row * Nc + col) = hv;
                } else if (EPI == 3) {
                    v0 = v0 + bias[col];
                    v1 = v1 + bias[col + 1];
                    __half2 hv; hv.x = __float2half_rn(v0); hv.y = __float2half_rn(v1);
                    *(__half2*)(Ch + row * Nc + col) = hv;
                } else {
                    float2 r = *(const float2*)(res + row * Nc + col);
                    *(float2*)(Cf + row * Nc + col) =
                        make_float2(v0 + bias[col] + r.x, v1 + bias[col + 1] + r.y);
                }
            }
        }
}

// ===================== launch ===============================================
extern "C" void kernel_launch(void* const* d_in, const int* in_sizes, int n_in,
                              void* d_out, int out_size)
{
    const float* points   = (const float*)d_in[0];
    const float* features = (const float*)d_in[1];
    const float* W_down   = (const float*)d_in[2];
    const float* b_down   = (const float*)d_in[3];
    const float* W_edge   = (const float*)d_in[4];
    const float* b_edge   = (const float*)d_in[5];
    const float* gamma    = (const float*)d_in[6];
    const float* beta     = (const float*)d_in[7];
    const float* mean     = (const float*)d_in[8];
    const float* var      = (const float*)d_in[9];
    const float* W_up     = (const float*)d_in[10];
    const float* b_up     = (const float*)d_in[11];
    float* out = (float*)d_out;

    const int SMEM_DYN = 65536;
    static bool init_done = false;
    static cudaStream_t s2 = nullptr;
    static cudaEvent_t ev_fork = nullptr, ev_join = nullptr;
    if (!init_done) {
        cudaFuncSetAttribute((const void*)gemm_f16<1>, cudaFuncAttributeMaxDynamicSharedMemorySize, SMEM_DYN);
        cudaFuncSetAttribute((const void*)gemm_f16<2>, cudaFuncAttributeMaxDynamicSharedMemorySize, SMEM_DYN);
        cudaFuncSetAttribute((const void*)gemm_f16<3>, cudaFuncAttributeMaxDynamicSharedMemorySize, SMEM_DYN);
        cudaStreamCreateWithFlags(&s2, cudaStreamNonBlocking);
        cudaEventCreateWithFlags(&ev_fork, cudaEventDisableTiming);
        cudaEventCreateWithFlags(&ev_join, cudaEventDisableTiming);
        init_done = true;
    }

    void *p_fa, *p_wd, *p_wc, *p_wu, *p_fl, *p_ab, *p_loc, *p_tf;
    cudaGetSymbolAddress(&p_fa,  g_fa);
    cudaGetSymbolAddress(&p_wd,  g_wdT);
    cudaGetSymbolAddress(&p_wc,  g_wcT);
    cudaGetSymbolAddress(&p_wu,  g_wuT);
    cudaGetSymbolAddress(&p_fl,  g_fl);
    cudaGetSymbolAddress(&p_ab,  g_AB);
    cudaGetSymbolAddress(&p_loc, g_loc);
    cudaGetSymbolAddress(&p_tf,  g_tf);

    // ---- fork: KNN on s2 ----
    cudaEventRecord(ev_fork, 0);
    cudaStreamWaitEvent(s2, ev_fork, 0);
    knn_kernel<<<dim3(NN / 8, BB), 256, 0, s2>>>(points);
    cudaEventRecord(ev_join, s2);

    // ---- main stream ----
    prep_all_kernel<<<(MM * DD / 4 + 255) / 256, 256>>>(
        (const float4*)features, W_down, W_edge, W_up,
        b_edge, gamma, beta, mean, var);

    gemm_f16<1><<<dim3(PP / 128, MM / 128), 256, SMEM_DYN>>>(
        (const __half*)p_fa, (const __half*)p_wd,
        DD, PP, (__half*)p_fl, nullptr, b_down, nullptr);

    gemm_f16<3><<<dim3(2 * PP / 128, MM / 128), 256, SMEM_DYN>>>(
        (const __half*)p_fl, (const __half*)p_wc,
        PP, 2 * PP, (__half*)p_ab, nullptr, (const float*)p_tf, nullptr);

    cudaStreamWaitEvent(0, ev_join, 0);
    edge_max_kernel<<<MM, 128>>>();

    gemm_f16<2><<<dim3(DD / 128, MM / 128), 256, SMEM_DYN>>>(
        (const __half*)p_loc, (const __half*)p_wu,
        PP, DD, nullptr, out, b_up, features);
}